// round 7
// baseline (speedup 1.0000x reference)
#include <cuda_runtime.h>
#include <cstdint>

#define OMEGA_ENC 0.01f
#define HD   64
#define LATD 32
#define SXF  68
#define N0MAX 4096
#define N1MAX 1024
#define ETMAX (16384 + 4096)
#define MAGICF 12582912.f   // 2^23 + 2^22

// ---------------- scratch ----------------
__device__ float  g_xf0[N0MAX*SXF];
__device__ float  g_xf1[N1MAX*SXF];
__device__ float  g_acc0[N0MAX*HD];
__device__ float  g_acc1[N1MAX*HD];
__device__ float  g_h1[N0MAX*HD];
__device__ float  g_pool[N0MAX*HD];
__device__ float  g_h2[N1MAX*HD];
__device__ float4 g_feat[ETMAX];
__device__ int    g_src[ETMAX];
__device__ int    g_dst[ETMAX];
__device__ float  g_edb[ETMAX];
__device__ float  g_Y[ETMAX*HD];
__device__ uint4  g_Bq[2][512];      // quantized 0.1*w1 in IMMA fragment-linear layout
__device__ float  g_invS[2];         // maxB / 127^2
__device__ float  g_w2p[2][HD*SXF];

// ---------------- helpers ----------------
__device__ __forceinline__ void imma(int* d, const uint32_t* a, uint32_t b0, uint32_t b1){
    asm volatile("mma.sync.aligned.m16n8k32.row.col.s32.s8.s8.s32 "
        "{%0,%1,%2,%3}, {%4,%5,%6,%7}, {%8,%9}, {%0,%1,%2,%3};"
        : "+r"(d[0]), "+r"(d[1]), "+r"(d[2]), "+r"(d[3])
        : "r"(a[0]), "r"(a[1]), "r"(a[2]), "r"(a[3]), "r"(b0), "r"(b1));
}
// quantize x (|x|<=1) to 2-level s8: hi=rni(x*127), lo=rni((x*127-hi)*128); bytes in .b0
__device__ __forceinline__ void quant2(float x, uint32_t& ih, uint32_t& il){
    float f1 = fmaf(x, 127.f, MAGICF);
    float a1 = f1 - MAGICF;
    float r  = fmaf(x, 127.f, -a1);
    float f2 = fmaf(r, 128.f, MAGICF);
    ih = __float_as_uint(f1); il = __float_as_uint(f2);
}
__device__ __forceinline__ uint32_t pack4(uint32_t b0, uint32_t b1, uint32_t b2, uint32_t b3){
    return __byte_perm(__byte_perm(b0, b1, 0x0040), __byte_perm(b2, b3, 0x0040), 0x5410);
}

// ---------------- prep: quantize B = 0.1*w1 into fragment layout ----------------
__global__ void k_prepB(const float* __restrict__ w1a, const float* __restrict__ w1b){
    int conv = blockIdx.x;
    const float* w1 = conv ? w1b : w1a;
    __shared__ float red[256];
    __shared__ float s_invMax;
    int tid = threadIdx.x;
    float m = 0.f;
    for (int i = tid; i < 4096; i += 256) m = fmaxf(m, fabsf(w1[i]));
    red[tid] = m; __syncthreads();
    for (int s = 128; s > 0; s >>= 1){
        if (tid < s) red[tid] = fmaxf(red[tid], red[tid+s]);
        __syncthreads();
    }
    if (tid == 0){
        float maxB = 0.1f * red[0];                 // max |0.1*w1|
        s_invMax = 1.f / red[0];                    // normalize w1 -> [-1,1]
        g_invS[conv] = maxB / 16129.f;              // maxB / 127^2
    }
    __syncthreads();
    float invMax = s_invMax;
    for (int i = tid; i < 512; i += 256){
        int kc = i >> 8, nt = (i >> 5) & 7, lane = i & 31;
        int g = lane >> 2, t = lane & 3;
        int n = nt*8 + g, k0 = kc*32 + 4*t;
        uint32_t ih[4], il[4], jh[4], jl[4];
        #pragma unroll
        for (int j = 0; j < 4; j++){
            quant2(w1[(k0+j   )*64 + n]*invMax, ih[j], il[j]);
            quant2(w1[(k0+16+j)*64 + n]*invMax, jh[j], jl[j]);
        }
        uint4 bq;
        bq.x = pack4(ih[0], ih[1], ih[2], ih[3]);   // b-frag reg0, hi split
        bq.y = pack4(jh[0], jh[1], jh[2], jh[3]);   // reg1, hi
        bq.z = pack4(il[0], il[1], il[2], il[3]);   // reg0, lo
        bq.w = pack4(jl[0], jl[1], jl[2], jl[3]);   // reg1, lo
        g_Bq[conv][i] = bq;
    }
}

// ---------------- prep: padded w2 ----------------
__global__ void k_prepW2(const float* __restrict__ w2a, const float* __restrict__ w2b){
    int i = blockIdx.x*blockDim.x + threadIdx.x;
    if (i >= 2*HD*SXF) return;
    int conv = i / (HD*SXF), j = i % (HD*SXF);
    int k = j / SXF, f = j % SXF;
    const float* w2 = conv ? w2b : w2a;
    g_w2p[conv][j] = (f < 67) ? w2[k*67 + f] : 0.f;
}

// ---------------- encoder (+acc0/pool init) ----------------
__global__ void k_enc(const float* __restrict__ x, const float* __restrict__ pos,
                      const float* __restrict__ w, const float* __restrict__ b){
    int i = blockIdx.x; int t = threadIdx.x;
    float s = b[t];
    #pragma unroll
    for (int f = 0; f < 8; f++) s += x[i*8+f]*w[f*HD+t];
    g_xf0[i*SXF+t] = sinf(OMEGA_ENC*s);
    if (t < 3) g_xf0[i*SXF+HD+t] = pos[i*3+t];
    g_acc0[i*HD+t] = 0.f;
    g_pool[i*HD+t] = __int_as_float(0xff800000);
}

// ---------------- prep: edge geometry + edotb ----------------
__global__ void k_prepEdge(const int* __restrict__ ei, int E, int Etot,
                           const float* __restrict__ pos, const float* __restrict__ xf,
                           const float* __restrict__ b2){
    int eg = blockIdx.x*blockDim.x + threadIdx.x;
    if (eg >= Etot) return;
    int src, dst;
    float f0 = 0.f, f1 = 0.f, f2 = 0.f;
    if (eg < E){
        src = ei[eg]; dst = ei[E+eg];
        float rx = pos[dst*3+0]-pos[src*3+0];
        float ry = pos[dst*3+1]-pos[src*3+1];
        float rz = pos[dst*3+2]-pos[src*3+2];
        if (!(rx == 0.f && ry == 0.f && rz == 0.f)){
            float rho = sqrtf(rx*rx+ry*ry+rz*rz);
            float th  = atan2f(ry, rx);
            float ratio = fminf(fmaxf(rz/rho, -1.f), 1.f);
            float ph  = asinf(ratio);
            const float inv_pi = 0.3183098861837907f;
            f0 = rho; f1 = th*inv_pi; f2 = ph*inv_pi;
        }
    } else { src = eg - E; dst = src; }
    g_feat[eg] = make_float4(f0, f1, f2, 0.f);
    g_src[eg] = src; g_dst[eg] = dst;
    const float* xr = xf + src*SXF;
    float db = 0.f;
    for (int f = 0; f < 67; f++) db += b2[f]*xr[f];
    g_edb[eg] = db;
}

// ---------------- prep: Y[e,k] ----------------
__global__ void k_prepY(const float* __restrict__ xf, const float* __restrict__ w2p,
                        int Etot){
    int idx = blockIdx.x*blockDim.x + threadIdx.x;
    int eg = idx >> 6, k = idx & 63;
    if (eg >= Etot) return;
    const float4* xr = (const float4*)(xf + g_src[eg]*SXF);
    const float4* wr = (const float4*)(w2p + k*SXF);
    float y = 0.f;
    #pragma unroll
    for (int i = 0; i < 17; i++){
        float4 a = xr[i], b = wr[i];
        y += a.x*b.x + a.y*b.y + a.z*b.z + a.w*b.w;
    }
    g_Y[eg*HD + k] = y;
}

// ---------------- IMMA kernel conv ----------------
__global__ __launch_bounds__(256, 2) void k_convTC(
    const float* __restrict__ w0, const float* __restrict__ b0,
    const float* __restrict__ b1, const uint4* __restrict__ Bq,
    const float* __restrict__ invSp,
    int Etot, int ntiles, float* __restrict__ acc)
{
    __shared__ __align__(16) uint4 smBq[512];
    __shared__ __align__(16) float sbase[2][64];
    __shared__ __align__(16) float sdel[64];
    __shared__ float sb1[64];
    __shared__ float s_inv;

    const int tid = threadIdx.x;
    smBq[tid] = Bq[tid];
    smBq[tid+256] = Bq[tid+256];
    if (tid < 64){ sdel[tid] = 0.1f*w0[192+tid]; sb1[tid] = 0.1f*b1[tid]; }
    if (tid == 0) s_inv = *invSp;

    const int w = tid >> 5, lane = tid & 31, g = lane >> 2, t = lane & 3;
    const int e  = w >> 2;            // edge slot
    const int cb = (w & 3) * 16;      // channel base for this warp
    const float c0 = (float)(cb + g);
    const float c1 = c0 + 8.f;
    const int e2 = tid >> 7, hb = tid & 63;   // base-gen mapping over ALL 256 threads

    __syncthreads();
    const float inv = s_inv;

    for (int tile = blockIdx.x; tile < ntiles; tile += gridDim.x){
        __syncthreads();
        {   // base generation: FIX — all 256 threads, e2 = tid>>7 covers both slots
            // (tid 0-63 and 64-127 write identical values to sbase[0]: benign)
            int eg = 2*tile + e2;
            float4 ft = (eg < Etot) ? g_feat[eg] : make_float4(0.f,0.f,0.f,0.f);
            sbase[e2][hb] = 0.1f*(ft.x*w0[hb] + ft.y*w0[64+hb] + ft.z*w0[128+hb] + b0[hb]);
        }
        __syncthreads();

        int d1[8][4], d2[8][4];
        #pragma unroll
        for (int nt = 0; nt < 8; nt++)
            #pragma unroll
            for (int q = 0; q < 4; q++){ d1[nt][q] = 0; d2[nt][q] = 0; }

        #pragma unroll
        for (int kc = 0; kc < 2; kc++){
            const int k0 = kc*32 + 4*t;
            float4 BA = *(const float4*)&sbase[e][k0];
            float4 DA = *(const float4*)&sdel[k0];
            float4 BB = *(const float4*)&sbase[e][k0+16];
            float4 DB = *(const float4*)&sdel[k0+16];

            uint32_t aH[4], aL[4];
            {
                uint32_t h0,l0,h1,l1,h2,l2,h3,l3;
                quant2(__sinf(fmaf(c0, DA.x, BA.x)), h0, l0);
                quant2(__sinf(fmaf(c0, DA.y, BA.y)), h1, l1);
                quant2(__sinf(fmaf(c0, DA.z, BA.z)), h2, l2);
                quant2(__sinf(fmaf(c0, DA.w, BA.w)), h3, l3);
                aH[0] = pack4(h0,h1,h2,h3); aL[0] = pack4(l0,l1,l2,l3);
                quant2(__sinf(fmaf(c1, DA.x, BA.x)), h0, l0);
                quant2(__sinf(fmaf(c1, DA.y, BA.y)), h1, l1);
                quant2(__sinf(fmaf(c1, DA.z, BA.z)), h2, l2);
                quant2(__sinf(fmaf(c1, DA.w, BA.w)), h3, l3);
                aH[1] = pack4(h0,h1,h2,h3); aL[1] = pack4(l0,l1,l2,l3);
                quant2(__sinf(fmaf(c0, DB.x, BB.x)), h0, l0);
                quant2(__sinf(fmaf(c0, DB.y, BB.y)), h1, l1);
                quant2(__sinf(fmaf(c0, DB.z, BB.z)), h2, l2);
                quant2(__sinf(fmaf(c0, DB.w, BB.w)), h3, l3);
                aH[2] = pack4(h0,h1,h2,h3); aL[2] = pack4(l0,l1,l2,l3);
                quant2(__sinf(fmaf(c1, DB.x, BB.x)), h0, l0);
                quant2(__sinf(fmaf(c1, DB.y, BB.y)), h1, l1);
                quant2(__sinf(fmaf(c1, DB.z, BB.z)), h2, l2);
                quant2(__sinf(fmaf(c1, DB.w, BB.w)), h3, l3);
                aH[3] = pack4(h0,h1,h2,h3); aL[3] = pack4(l0,l1,l2,l3);
            }
            const uint4* bp = &smBq[(kc << 8) + lane];
            #pragma unroll
            for (int nt = 0; nt < 8; nt++){
                uint4 bq = bp[nt << 5];
                imma(d1[nt], aH, bq.x, bq.y);   // a1*b1
                imma(d2[nt], aL, bq.x, bq.y);   // a2*b1
                imma(d2[nt], aH, bq.z, bq.w);   // a1*b2
            }
        }

        // ---- epilogue: D = (d1 + d2/128) * maxB/127^2 ----
        int eg = 2*tile + e;
        bool val = (eg < Etot);
        float msg0 = 0.f, msg1 = 0.f;
        #pragma unroll
        for (int nt = 0; nt < 8; nt++){
            int col = nt*8 + 2*t;
            float2 bv = *(const float2*)&sb1[col];
            float2 yv = val ? *(const float2*)&g_Y[eg*HD + col] : make_float2(0.f,0.f);
            float v00 = fmaf(fmaf(__int2float_rn(d2[nt][0]), 0.0078125f, __int2float_rn(d1[nt][0])), inv, bv.x);
            float v01 = fmaf(fmaf(__int2float_rn(d2[nt][1]), 0.0078125f, __int2float_rn(d1[nt][1])), inv, bv.y);
            float v10 = fmaf(fmaf(__int2float_rn(d2[nt][2]), 0.0078125f, __int2float_rn(d1[nt][2])), inv, bv.x);
            float v11 = fmaf(fmaf(__int2float_rn(d2[nt][3]), 0.0078125f, __int2float_rn(d1[nt][3])), inv, bv.y);
            msg0 += __sinf(v00)*yv.x + __sinf(v01)*yv.y;
            msg1 += __sinf(v10)*yv.x + __sinf(v11)*yv.y;
        }
        msg0 += __shfl_xor_sync(~0u, msg0, 1); msg0 += __shfl_xor_sync(~0u, msg0, 2);
        msg1 += __shfl_xor_sync(~0u, msg1, 1); msg1 += __shfl_xor_sync(~0u, msg1, 2);
        if (t == 0 && val){
            int dst = g_dst[eg];
            float eb = g_edb[eg];
            atomicAdd(&acc[dst*HD + cb + g    ], msg0 + eb);
            atomicAdd(&acc[dst*HD + cb + g + 8], msg1 + eb);
        }
    }
}

// ---------------- post / pool / gather / final ----------------
__global__ void k_post(const float* __restrict__ acc, const float* __restrict__ bias,
                       float* __restrict__ out, int n){
    int i = blockIdx.x*blockDim.x + threadIdx.x;
    if (i < n) out[i] = sinf(OMEGA_ENC*(acc[i] + bias[i & 63]));
}
__device__ __forceinline__ void atomicMaxF(float* addr, float v){
    if (__float_as_uint(v) == 0x80000000u) v = 0.f;
    if (v >= 0.f) atomicMax((int*)addr, __float_as_int(v));
    else          atomicMin((unsigned int*)addr, __float_as_uint(v));
}
__global__ void k_pool(int Etot){
    int idx = blockIdx.x*blockDim.x + threadIdx.x;
    int e = idx >> 6, c = idx & 63;
    if (e >= Etot) return;
    atomicMaxF(&g_pool[g_dst[e]*HD + c], g_h1[g_src[e]*HD + c]);
}
__global__ void k_xf1(const int* __restrict__ keep, const float* __restrict__ pos1){
    int j = blockIdx.x, t = threadIdx.x;
    if (t < HD){
        g_xf1[j*SXF+t] = g_pool[keep[j]*HD + t];
        g_acc1[j*HD+t] = 0.f;
    } else if (t < HD+3) g_xf1[j*SXF+t] = pos1[j*3 + (t - HD)];
}
__global__ void k_final(const float* __restrict__ w, const float* __restrict__ b,
                        float* __restrict__ out){
    int j = blockIdx.x, l = threadIdx.x;
    float s = b[l];
    #pragma unroll
    for (int c = 0; c < HD; c++) s += g_h2[j*HD+c]*w[c*LATD+l];
    out[j*LATD+l] = sinf(OMEGA_ENC*s);
}

// ---------------- launch ----------------
extern "C" void kernel_launch(void* const* d_in, const int* in_sizes, int n_in,
                              void* d_out, int out_size){
    int iPos = 1, iEi = 2;
    if (in_sizes[1] == in_sizes[0]) { iEi = 1; iPos = 2; }

    const float* x      = (const float*)d_in[0];
    const float* pos    = (const float*)d_in[iPos];
    const int*   ei     = (const int*)  d_in[iEi];
    const int*   ei1    = (const int*)  d_in[3];
    const float* pos1   = (const float*)d_in[4];
    const int*   keep   = (const int*)  d_in[5];
    const float* lin0_w = (const float*)d_in[6];
    const float* lin0_b = (const float*)d_in[7];
    const float* lin1_w = (const float*)d_in[8];
    const float* lin1_b = (const float*)d_in[9];
    const float* c0p[7]; for (int i = 0; i < 7; i++) c0p[i] = (const float*)d_in[10+i];
    const float* c1p[7]; for (int i = 0; i < 7; i++) c1p[i] = (const float*)d_in[17+i];

    int N0 = in_sizes[0] / 8;
    int E0 = in_sizes[iEi] / 2;
    int N1 = in_sizes[5];
    int E1 = in_sizes[3] / 2;
    int Et0 = E0 + N0, Et1 = E1 + N1;
    int nt0 = (Et0 + 1)/2, nt1 = (Et1 + 1)/2;
    float* out = (float*)d_out;

    float *xf0, *acc0, *h1, *xf1, *acc1, *h2, *w2p, *invS;
    uint4* bq;
    cudaGetSymbolAddress((void**)&xf0,  g_xf0);
    cudaGetSymbolAddress((void**)&acc0, g_acc0);
    cudaGetSymbolAddress((void**)&h1,   g_h1);
    cudaGetSymbolAddress((void**)&xf1,  g_xf1);
    cudaGetSymbolAddress((void**)&acc1, g_acc1);
    cudaGetSymbolAddress((void**)&h2,   g_h2);
    cudaGetSymbolAddress((void**)&bq,   g_Bq);
    cudaGetSymbolAddress((void**)&invS, g_invS);
    cudaGetSymbolAddress((void**)&w2p,  g_w2p);

    int g0 = nt0 < 296 ? nt0 : 296;
    int g1 = nt1 < 296 ? nt1 : 296;

    k_prepB <<<2, 256>>>(c0p[2], c1p[2]);
    k_prepW2<<<(2*HD*SXF + 255)/256, 256>>>(c0p[4], c1p[4]);
    k_enc   <<<N0, HD>>>(x, pos, lin0_w, lin0_b);

    // ---- conv0 ----
    k_prepEdge<<<(Et0 + 127)/128, 128>>>(ei, E0, Et0, pos, xf0, c0p[5]);
    k_prepY   <<<(Et0*HD + 127)/128, 128>>>(xf0, w2p, Et0);
    k_convTC  <<<g0, 256>>>(c0p[0], c0p[1], c0p[3], bq, invS, Et0, nt0, acc0);
    k_post    <<<(N0*HD + 255)/256, 256>>>(acc0, c0p[6], h1, N0*HD);

    // ---- pool ----
    k_pool<<<(Et0*HD + 255)/256, 256>>>(Et0);
    k_xf1 <<<N1, 96>>>(keep, pos1);

    // ---- conv1 ----
    k_prepEdge<<<(Et1 + 127)/128, 128>>>(ei1, E1, Et1, pos1, xf1, c1p[5]);
    k_prepY   <<<(Et1*HD + 127)/128, 128>>>(xf1, w2p + HD*SXF, Et1);
    k_convTC  <<<g1, 256>>>(c1p[0], c1p[1], c1p[3], bq + 512, invS + 1, Et1, nt1, acc1);
    k_post    <<<(N1*HD + 255)/256, 256>>>(acc1, c1p[6], h2, N1*HD);

    k_final<<<N1, LATD>>>(lin1_w, lin1_b, out);
}

// round 8
// speedup vs baseline: 2.4632x; 2.4632x over previous
#include <cuda_runtime.h>
#include <cuda_fp16.h>
#include <cstdint>

#define OMEGA_ENC 0.01f
#define HD   64
#define LATD 32
#define SXF  68          // padded xf row stride
#define YST  72          // Y row stride: cols 0-63 = y_k, col 64 = edb
#define W2R  72          // padded w2 rows: 0-63 = w2, 64 = b2, 65-71 = 0
#define N0MAX 4096
#define N1MAX 1024
#define ETMAX (16384 + 4096)

// ---------------- scratch ----------------
__device__ float  g_xf0[N0MAX*SXF];
__device__ float  g_xf1[N1MAX*SXF];
__device__ float  g_acc0[N0MAX*HD];
__device__ float  g_acc1[N1MAX*HD];
__device__ float  g_h1[N0MAX*HD];
__device__ float  g_pool[N0MAX*HD];
__device__ float  g_h2[N1MAX*HD];
__device__ float4 g_feat[ETMAX];
__device__ int    g_src[ETMAX];
__device__ int    g_dst[ETMAX];
__device__ float  g_Y[ETMAX*YST];
__device__ __half g_Bt[2][4096];        // fp16(0.1*w1), ldmatrix 8x8 tile layout
__device__ float  g_w2p[2][W2R*SXF];

// ---------------- helpers ----------------
__device__ __forceinline__ uint32_t smem_u32(const void* p){
    uint32_t a;
    asm("{ .reg .u64 t; cvta.to.shared.u64 t, %1; cvt.u32.u64 %0, t; }" : "=r"(a) : "l"(p));
    return a;
}
__device__ __forceinline__ void split2(float v0, float v1, uint32_t& hi, uint32_t& lo){
    __half2 h = __floats2half2_rn(v0, v1);
    float2 hf = __half22float2(h);
    __half2 l2 = __floats2half2_rn(v0 - hf.x, v1 - hf.y);
    hi = *reinterpret_cast<uint32_t*>(&h);
    lo = *reinterpret_cast<uint32_t*>(&l2);
}
__device__ __forceinline__ void mma16816(float* d, const uint32_t* a, uint32_t b0, uint32_t b1){
    asm volatile("mma.sync.aligned.m16n8k16.row.col.f32.f16.f16.f32 "
        "{%0,%1,%2,%3}, {%4,%5,%6,%7}, {%8,%9}, {%0,%1,%2,%3};"
        : "+f"(d[0]), "+f"(d[1]), "+f"(d[2]), "+f"(d[3])
        : "r"(a[0]), "r"(a[1]), "r"(a[2]), "r"(a[3]), "r"(b0), "r"(b1));
}

// ---------------- prep: B tiles (fp16 of 0.1*w1, 8x8 tile layout) --------------
// group = (k2*8+nt)*2 + kh ; tile[r][c]: h = k2*16 + kh*8 + r, n = nt*8 + c
__global__ void k_prepB(const float* __restrict__ w1a, const float* __restrict__ w1b){
    int i = blockIdx.x*blockDim.x + threadIdx.x;
    if (i >= 2*4096) return;
    int conv = i >> 12, j = i & 4095;
    int group = j >> 6, rc = j & 63;
    int kh = group & 1, gnt = group >> 1;
    int k2 = gnt >> 3, nt = gnt & 7;
    int r = rc >> 3, c = rc & 7;
    int h = k2*16 + kh*8 + r;
    int n = nt*8 + c;
    const float* w1 = conv ? w1b : w1a;
    g_Bt[conv][j] = __float2half_rn(0.1f * w1[h*HD + n]);
}

// ---------------- prep: padded w2 (row 64 = b2) ----------------
__global__ void k_prepW2(const float* __restrict__ w2a, const float* __restrict__ w2b,
                         const float* __restrict__ b2a, const float* __restrict__ b2b){
    int i = blockIdx.x*blockDim.x + threadIdx.x;
    if (i >= 2*W2R*SXF) return;
    int conv = i / (W2R*SXF), j = i % (W2R*SXF);
    int k = j / SXF, f = j % SXF;
    const float* w2 = conv ? w2b : w2a;
    const float* b2 = conv ? b2b : b2a;
    float v = 0.f;
    if (f < 67){
        if (k < 64) v = w2[k*67 + f];
        else if (k == 64) v = b2[f];
    }
    g_w2p[conv][j] = v;
}

// ---------------- encoder (+acc0/pool init) ----------------
__global__ void k_enc(const float* __restrict__ x, const float* __restrict__ pos,
                      const float* __restrict__ w, const float* __restrict__ b){
    int i = blockIdx.x; int t = threadIdx.x;
    float s = b[t];
    #pragma unroll
    for (int f = 0; f < 8; f++) s += x[i*8+f]*w[f*HD+t];
    g_xf0[i*SXF+t] = sinf(OMEGA_ENC*s);
    if (t < 3) g_xf0[i*SXF+HD+t] = pos[i*3+t];
    g_acc0[i*HD+t] = 0.f;
    g_pool[i*HD+t] = __int_as_float(0xff800000);
}

// ---------------- prep: edge geometry only ----------------
__global__ void k_prepEdge(const int* __restrict__ ei, int E, int Etot,
                           const float* __restrict__ pos){
    int eg = blockIdx.x*blockDim.x + threadIdx.x;
    if (eg >= Etot) return;
    int src, dst;
    float f0 = 0.f, f1 = 0.f, f2 = 0.f;
    if (eg < E){
        src = ei[eg]; dst = ei[E+eg];
        float rx = pos[dst*3+0]-pos[src*3+0];
        float ry = pos[dst*3+1]-pos[src*3+1];
        float rz = pos[dst*3+2]-pos[src*3+2];
        if (!(rx == 0.f && ry == 0.f && rz == 0.f)){
            float rho = sqrtf(rx*rx+ry*ry+rz*rz);
            float th  = atan2f(ry, rx);
            float ratio = fminf(fmaxf(rz/rho, -1.f), 1.f);
            float ph  = asinf(ratio);
            const float inv_pi = 0.3183098861837907f;
            f0 = rho; f1 = th*inv_pi; f2 = ph*inv_pi;
        }
    } else { src = eg - E; dst = src; }
    g_feat[eg] = make_float4(f0, f1, f2, 0.f);
    g_src[eg] = src; g_dst[eg] = dst;
}

// ---------------- prep: Y[e,k] = w2p[k,:] . xf[src_e]  (k=64 gives edb) --------
__global__ void k_prepY(const float* __restrict__ xf, const float* __restrict__ w2p,
                        int Etot){
    int idx = blockIdx.x*blockDim.x + threadIdx.x;
    int eg = idx / YST, k = idx - eg*YST;
    if (eg >= Etot || k > 64) return;
    const float4* xr = (const float4*)(xf + g_src[eg]*SXF);
    const float4* wr = (const float4*)(w2p + k*SXF);
    float y = 0.f;
    #pragma unroll
    for (int i = 0; i < 17; i++){
        float4 a = xr[i], b = wr[i];
        y += a.x*b.x + a.y*b.y + a.z*b.z + a.w*b.w;
    }
    g_Y[eg*YST + k] = y;
}

// ---------------- HMMA kernel conv (2-term split) ----------------
// Tile = 2 edges (M=128 rows: m = 64e + c).  4 warps; warp w owns m-strips
// 32w and 32w+16.  A = sin(base_e[h] + c*del[h]) split fp16 hi/lo in regs;
// B = fp16(0.1*w1) via ldmatrix.x2; D = Ah*B + Al*B (fp32 accum).
__global__ __launch_bounds__(128, 4) void k_convTC(
    const float* __restrict__ w0, const float* __restrict__ b0,
    const float* __restrict__ b1, const __half* __restrict__ Bt,
    int Etot, int ntiles, float* __restrict__ acc)
{
    __shared__ __align__(16) __half smB[4096];
    __shared__ float sbase[2][64];
    __shared__ float sdel[64];
    __shared__ float sb1[64];

    const int tid = threadIdx.x;
    {
        const uint4* s = (const uint4*)Bt;
        uint4* d = (uint4*)smB;
        #pragma unroll
        for (int i = 0; i < 4; i++) d[tid + 128*i] = s[tid + 128*i];
    }
    if (tid < 64){ sdel[tid] = 0.1f*w0[192+tid]; sb1[tid] = 0.1f*b1[tid]; }

    const int hb = tid & 63;
    const float w0a = w0[hb], w0b_ = w0[64+hb], w0c = w0[128+hb], b0h = b0[hb];

    const int w = tid >> 5, l = tid & 31, g = l >> 2, t = l & 3;
    const int e  = w >> 1;
    const int cb = 32*(w & 1);
    const int e2 = tid >> 6;
    const uint32_t lm_base = smem_u32(smB) +
        (uint32_t)(((((l >> 3) & 1)*64) + (l & 7)*8) * 2);

    __syncthreads();

    for (int tile = blockIdx.x; tile < ntiles; tile += gridDim.x){
        __syncthreads();
        {   // base generation: thread (e2 = tid>>6, hb)
            int eg = 2*tile + e2;
            float4 ft = (eg < Etot) ? g_feat[eg] : make_float4(0.f,0.f,0.f,0.f);
            sbase[e2][hb] = 0.1f*(ft.x*w0a + ft.y*w0b_ + ft.z*w0c + b0h);
        }
        __syncthreads();

        float d[2][8][4];
        #pragma unroll
        for (int s = 0; s < 2; s++)
            #pragma unroll
            for (int n = 0; n < 8; n++)
                #pragma unroll
                for (int q = 0; q < 4; q++) d[s][n][q] = 0.f;

        #pragma unroll
        for (int k2 = 0; k2 < 4; k2++){
            const int hA = 2*t + 16*k2;
            float2 bA = *(const float2*)&sbase[e][hA];
            float2 dA = *(const float2*)&sdel[hA];
            float2 bB = *(const float2*)&sbase[e][hA+8];
            float2 dB = *(const float2*)&sdel[hA+8];

            uint32_t aH[2][4], aL[2][4];
            #pragma unroll
            for (int s = 0; s < 2; s++){
                float cf = (float)(cb + 16*s + g);
                float a00 = __sinf(fmaf(cf,     dA.x, bA.x));
                float a01 = __sinf(fmaf(cf,     dA.y, bA.y));
                float a10 = __sinf(fmaf(cf+8.f, dA.x, bA.x));
                float a11 = __sinf(fmaf(cf+8.f, dA.y, bA.y));
                float a20 = __sinf(fmaf(cf,     dB.x, bB.x));
                float a21 = __sinf(fmaf(cf,     dB.y, bB.y));
                float a30 = __sinf(fmaf(cf+8.f, dB.x, bB.x));
                float a31 = __sinf(fmaf(cf+8.f, dB.y, bB.y));
                split2(a00, a01, aH[s][0], aL[s][0]);
                split2(a10, a11, aH[s][1], aL[s][1]);
                split2(a20, a21, aH[s][2], aL[s][2]);
                split2(a30, a31, aH[s][3], aL[s][3]);
            }
            uint32_t lma = lm_base + (uint32_t)(k2*8)*256u;
            #pragma unroll
            for (int nt = 0; nt < 8; nt++){
                uint32_t r0, r1;
                asm volatile("ldmatrix.sync.aligned.m8n8.x2.trans.shared.b16 "
                             "{%0,%1}, [%2];"
                             : "=r"(r0), "=r"(r1) : "r"(lma));
                lma += 256u;
                #pragma unroll
                for (int s = 0; s < 2; s++){
                    mma16816(d[s][nt], aH[s], r0, r1);
                    mma16816(d[s][nt], aL[s], r0, r1);
                }
            }
        }

        // ---- epilogue ----
        int eg = 2*tile + e;
        bool val = (eg < Etot);
        float m00 = 0.f, m01 = 0.f, m10 = 0.f, m11 = 0.f;
        #pragma unroll
        for (int nt = 0; nt < 8; nt++){
            int col = 2*t + 8*nt;
            float2 bv = *(const float2*)&sb1[col];
            float2 yv = val ? *(const float2*)&g_Y[eg*YST + col] : make_float2(0.f, 0.f);
            m00 += __sinf(d[0][nt][0]+bv.x)*yv.x + __sinf(d[0][nt][1]+bv.y)*yv.y;
            m01 += __sinf(d[0][nt][2]+bv.x)*yv.x + __sinf(d[0][nt][3]+bv.y)*yv.y;
            m10 += __sinf(d[1][nt][0]+bv.x)*yv.x + __sinf(d[1][nt][1]+bv.y)*yv.y;
            m11 += __sinf(d[1][nt][2]+bv.x)*yv.x + __sinf(d[1][nt][3]+bv.y)*yv.y;
        }
        m00 += __shfl_xor_sync(~0u, m00, 1); m00 += __shfl_xor_sync(~0u, m00, 2);
        m01 += __shfl_xor_sync(~0u, m01, 1); m01 += __shfl_xor_sync(~0u, m01, 2);
        m10 += __shfl_xor_sync(~0u, m10, 1); m10 += __shfl_xor_sync(~0u, m10, 2);
        m11 += __shfl_xor_sync(~0u, m11, 1); m11 += __shfl_xor_sync(~0u, m11, 2);
        if (t == 0 && val){
            int dst = g_dst[eg];
            float eb = g_Y[eg*YST + 64];
            atomicAdd(&acc[dst*HD + cb + g     ], m00 + eb);
            atomicAdd(&acc[dst*HD + cb + g + 8 ], m01 + eb);
            atomicAdd(&acc[dst*HD + cb + g + 16], m10 + eb);
            atomicAdd(&acc[dst*HD + cb + g + 24], m11 + eb);
        }
    }
}

// ---------------- post / pool / gather / final ----------------
__global__ void k_post(const float* __restrict__ acc, const float* __restrict__ bias,
                       float* __restrict__ out, int n){
    int i = blockIdx.x*blockDim.x + threadIdx.x;
    if (i < n) out[i] = sinf(OMEGA_ENC*(acc[i] + bias[i & 63]));
}
__device__ __forceinline__ void atomicMaxF(float* addr, float v){
    if (__float_as_uint(v) == 0x80000000u) v = 0.f;
    if (v >= 0.f) atomicMax((int*)addr, __float_as_int(v));
    else          atomicMin((unsigned int*)addr, __float_as_uint(v));
}
__global__ void k_pool(int Etot){
    int idx = blockIdx.x*blockDim.x + threadIdx.x;
    int e = idx >> 6, c = idx & 63;
    if (e >= Etot) return;
    atomicMaxF(&g_pool[g_dst[e]*HD + c], g_h1[g_src[e]*HD + c]);
}
__global__ void k_xf1(const int* __restrict__ keep, const float* __restrict__ pos1){
    int j = blockIdx.x, t = threadIdx.x;
    if (t < HD){
        g_xf1[j*SXF+t] = g_pool[keep[j]*HD + t];
        g_acc1[j*HD+t] = 0.f;
    } else if (t < HD+3) g_xf1[j*SXF+t] = pos1[j*3 + (t - HD)];
}
__global__ void k_final(const float* __restrict__ w, const float* __restrict__ b,
                        float* __restrict__ out){
    int j = blockIdx.x, l = threadIdx.x;
    float s = b[l];
    #pragma unroll
    for (int c = 0; c < HD; c++) s += g_h2[j*HD+c]*w[c*LATD+l];
    out[j*LATD+l] = sinf(OMEGA_ENC*s);
}

// ---------------- launch ----------------
extern "C" void kernel_launch(void* const* d_in, const int* in_sizes, int n_in,
                              void* d_out, int out_size){
    int iPos = 1, iEi = 2;
    if (in_sizes[1] == in_sizes[0]) { iEi = 1; iPos = 2; }

    const float* x      = (const float*)d_in[0];
    const float* pos    = (const float*)d_in[iPos];
    const int*   ei     = (const int*)  d_in[iEi];
    const int*   ei1    = (const int*)  d_in[3];
    const float* pos1   = (const float*)d_in[4];
    const int*   keep   = (const int*)  d_in[5];
    const float* lin0_w = (const float*)d_in[6];
    const float* lin0_b = (const float*)d_in[7];
    const float* lin1_w = (const float*)d_in[8];
    const float* lin1_b = (const float*)d_in[9];
    const float* c0p[7]; for (int i = 0; i < 7; i++) c0p[i] = (const float*)d_in[10+i];
    const float* c1p[7]; for (int i = 0; i < 7; i++) c1p[i] = (const float*)d_in[17+i];

    int N0 = in_sizes[0] / 8;
    int E0 = in_sizes[iEi] / 2;
    int N1 = in_sizes[5];
    int E1 = in_sizes[3] / 2;
    int Et0 = E0 + N0, Et1 = E1 + N1;
    int nt0 = (Et0 + 1)/2, nt1 = (Et1 + 1)/2;
    float* out = (float*)d_out;

    float *xf0, *acc0, *h1, *xf1, *acc1, *h2, *w2p;
    __half* bt;
    cudaGetSymbolAddress((void**)&xf0,  g_xf0);
    cudaGetSymbolAddress((void**)&acc0, g_acc0);
    cudaGetSymbolAddress((void**)&h1,   g_h1);
    cudaGetSymbolAddress((void**)&xf1,  g_xf1);
    cudaGetSymbolAddress((void**)&acc1, g_acc1);
    cudaGetSymbolAddress((void**)&h2,   g_h2);
    cudaGetSymbolAddress((void**)&bt,   g_Bt);
    cudaGetSymbolAddress((void**)&w2p,  g_w2p);

    int g0 = nt0 < 592 ? nt0 : 592;
    int g1 = nt1 < 592 ? nt1 : 592;

    k_prepB <<<32, 256>>>(c0p[2], c1p[2]);
    k_prepW2<<<(2*W2R*SXF + 255)/256, 256>>>(c0p[4], c1p[4], c0p[5], c1p[5]);
    k_enc   <<<N0, HD>>>(x, pos, lin0_w, lin0_b);

    // ---- conv0 ----
    k_prepEdge<<<(Et0 + 127)/128, 128>>>(ei, E0, Et0, pos);
    k_prepY   <<<(Et0*YST + 255)/256, 256>>>(xf0, w2p, Et0);
    k_convTC  <<<g0, 128>>>(c0p[0], c0p[1], c0p[3], bt, Et0, nt0, acc0);
    k_post    <<<(N0*HD + 255)/256, 256>>>(acc0, c0p[6], h1, N0*HD);

    // ---- pool ----
    k_pool<<<(Et0*HD + 255)/256, 256>>>(Et0);
    k_xf1 <<<N1, 96>>>(keep, pos1);

    // ---- conv1 ----
    k_prepEdge<<<(Et1 + 127)/128, 128>>>(ei1, E1, Et1, pos1);
    k_prepY   <<<(Et1*YST + 255)/256, 256>>>(xf1, w2p + W2R*SXF, Et1);
    k_convTC  <<<g1, 128>>>(c1p[0], c1p[1], c1p[3], bt + 4096, Et1, nt1, acc1);
    k_post    <<<(N1*HD + 255)/256, 256>>>(acc1, c1p[6], h2, N1*HD);

    k_final<<<N1, LATD>>>(lin1_w, lin1_b, out);
}

// round 9
// speedup vs baseline: 2.9539x; 1.1992x over previous
#include <cuda_runtime.h>
#include <cuda_fp16.h>
#include <cstdint>

#define OMEGA_ENC 0.01f
#define HD   64
#define LATD 32
#define SXF  68          // padded xf row stride
#define YST  72          // Y row stride: cols 0-63 = y_k, col 64 = edb
#define W2R  72          // padded w2 rows: 0-63 = w2, 64 = b2, 65-71 = 0
#define N0MAX 4096
#define N1MAX 1024
#define ETMAX (16384 + 4096)

// ---------------- scratch ----------------
__device__ float  g_xf0[N0MAX*SXF];
__device__ float  g_xf1[N1MAX*SXF];
__device__ float  g_acc0[N0MAX*HD];
__device__ float  g_acc1[N1MAX*HD];
__device__ float  g_h1[N0MAX*HD];
__device__ float  g_pool[N0MAX*HD];
__device__ float  g_h2[N1MAX*HD];
__device__ float4 g_feat[ETMAX];
__device__ int    g_src[ETMAX];
__device__ int    g_dst[ETMAX];
__device__ float  g_Y[ETMAX*YST];
__device__ __half g_Bt[2][4096];        // fp16(0.1*w1), ldmatrix 8x8 tile layout
__device__ float  g_w2p[2][W2R*SXF];

// ---------------- helpers ----------------
__device__ __forceinline__ uint32_t smem_u32(const void* p){
    uint32_t a;
    asm("{ .reg .u64 t; cvta.to.shared.u64 t, %1; cvt.u32.u64 %0, t; }" : "=r"(a) : "l"(p));
    return a;
}
__device__ __forceinline__ uint32_t packh2(float v0, float v1){
    __half2 h = __floats2half2_rn(v0, v1);
    return *reinterpret_cast<uint32_t*>(&h);
}
__device__ __forceinline__ void mma16816(float* d, const uint32_t* a, uint32_t b0, uint32_t b1){
    asm volatile("mma.sync.aligned.m16n8k16.row.col.f32.f16.f16.f32 "
        "{%0,%1,%2,%3}, {%4,%5,%6,%7}, {%8,%9}, {%0,%1,%2,%3};"
        : "+f"(d[0]), "+f"(d[1]), "+f"(d[2]), "+f"(d[3])
        : "r"(a[0]), "r"(a[1]), "r"(a[2]), "r"(a[3]), "r"(b0), "r"(b1));
}

// ---------------- prep: B tiles (fp16 of 0.1*w1, 8x8 tile layout) --------------
__global__ void k_prepB(const float* __restrict__ w1a, const float* __restrict__ w1b){
    int i = blockIdx.x*blockDim.x + threadIdx.x;
    if (i >= 2*4096) return;
    int conv = i >> 12, j = i & 4095;
    int group = j >> 6, rc = j & 63;
    int kh = group & 1, gnt = group >> 1;
    int k2 = gnt >> 3, nt = gnt & 7;
    int r = rc >> 3, c = rc & 7;
    int h = k2*16 + kh*8 + r;
    int n = nt*8 + c;
    const float* w1 = conv ? w1b : w1a;
    g_Bt[conv][j] = __float2half_rn(0.1f * w1[h*HD + n]);
}

// ---------------- prep: padded w2 (row 64 = b2) ----------------
__global__ void k_prepW2(const float* __restrict__ w2a, const float* __restrict__ w2b,
                         const float* __restrict__ b2a, const float* __restrict__ b2b){
    int i = blockIdx.x*blockDim.x + threadIdx.x;
    if (i >= 2*W2R*SXF) return;
    int conv = i / (W2R*SXF), j = i % (W2R*SXF);
    int k = j / SXF, f = j % SXF;
    const float* w2 = conv ? w2b : w2a;
    const float* b2 = conv ? b2b : b2a;
    float v = 0.f;
    if (f < 67){
        if (k < 64) v = w2[k*67 + f];
        else if (k == 64) v = b2[f];
    }
    g_w2p[conv][j] = v;
}

// ---------------- encoder (+acc0 init) ----------------
__global__ void k_enc(const float* __restrict__ x, const float* __restrict__ pos,
                      const float* __restrict__ w, const float* __restrict__ b){
    int i = blockIdx.x; int t = threadIdx.x;
    float s = b[t];
    #pragma unroll
    for (int f = 0; f < 8; f++) s += x[i*8+f]*w[f*HD+t];
    g_xf0[i*SXF+t] = sinf(OMEGA_ENC*s);
    if (t < 3) g_xf0[i*SXF+HD+t] = pos[i*3+t];
    g_acc0[i*HD+t] = 0.f;
}

// ---------------- prep: fused edge geometry + Y ----------------
// thread (eg, k): k<=64 -> Y[eg,k] = w2p[k,:].xf[src]; k==65 -> geometry/feat/src/dst
__global__ void k_prepEY(const int* __restrict__ ei, int E, int Etot,
                         const float* __restrict__ pos, const float* __restrict__ xf,
                         const float* __restrict__ w2p){
    int idx = blockIdx.x*blockDim.x + threadIdx.x;
    int eg = idx / YST, k = idx - eg*YST;
    if (eg >= Etot) return;
    int src = (eg < E) ? ei[eg] : (eg - E);
    if (k <= 64){
        const float4* xr = (const float4*)(xf + src*SXF);
        const float4* wr = (const float4*)(w2p + k*SXF);
        float y = 0.f;
        #pragma unroll
        for (int i = 0; i < 17; i++){
            float4 a = xr[i], b = wr[i];
            y += a.x*b.x + a.y*b.y + a.z*b.z + a.w*b.w;
        }
        g_Y[eg*YST + k] = y;
    } else if (k == 65){
        int dst = src;
        float f0 = 0.f, f1 = 0.f, f2 = 0.f;
        if (eg < E){
            dst = ei[E+eg];
            float rx = pos[dst*3+0]-pos[src*3+0];
            float ry = pos[dst*3+1]-pos[src*3+1];
            float rz = pos[dst*3+2]-pos[src*3+2];
            if (!(rx == 0.f && ry == 0.f && rz == 0.f)){
                float rho = sqrtf(rx*rx+ry*ry+rz*rz);
                float th  = atan2f(ry, rx);
                float ratio = fminf(fmaxf(rz/rho, -1.f), 1.f);
                float ph  = asinf(ratio);
                const float inv_pi = 0.3183098861837907f;
                f0 = rho; f1 = th*inv_pi; f2 = ph*inv_pi;
            }
        }
        g_feat[eg] = make_float4(f0, f1, f2, 0.f);
        g_src[eg] = src; g_dst[eg] = dst;
    }
}

// ---------------- HMMA kernel conv (single-term fp16) ----------------
__global__ __launch_bounds__(128, 4) void k_convTC(
    const float* __restrict__ w0, const float* __restrict__ b0,
    const float* __restrict__ b1, const __half* __restrict__ Bt,
    int Etot, int ntiles, float* __restrict__ acc)
{
    __shared__ __align__(16) __half smB[4096];
    __shared__ float sbase[2][64];
    __shared__ float sdel[64];
    __shared__ float sb1[64];

    const int tid = threadIdx.x;
    {
        const uint4* s = (const uint4*)Bt;
        uint4* d = (uint4*)smB;
        #pragma unroll
        for (int i = 0; i < 4; i++) d[tid + 128*i] = s[tid + 128*i];
    }
    if (tid < 64){ sdel[tid] = 0.1f*w0[192+tid]; sb1[tid] = 0.1f*b1[tid]; }

    const int hb = tid & 63;
    const float w0a = w0[hb], w0b_ = w0[64+hb], w0c = w0[128+hb], b0h = b0[hb];

    const int w = tid >> 5, l = tid & 31, g = l >> 2, t = l & 3;
    const int e  = w >> 1;
    const int cb = 32*(w & 1);
    const int e2 = tid >> 6;
    const uint32_t lm_base = smem_u32(smB) +
        (uint32_t)(((((l >> 3) & 1)*64) + (l & 7)*8) * 2);

    __syncthreads();

    for (int tile = blockIdx.x; tile < ntiles; tile += gridDim.x){
        __syncthreads();
        {   // base generation: thread (e2 = tid>>6, hb)
            int eg = 2*tile + e2;
            float4 ft = (eg < Etot) ? g_feat[eg] : make_float4(0.f,0.f,0.f,0.f);
            sbase[e2][hb] = 0.1f*(ft.x*w0a + ft.y*w0b_ + ft.z*w0c + b0h);
        }
        __syncthreads();

        float d[2][8][4];
        #pragma unroll
        for (int s = 0; s < 2; s++)
            #pragma unroll
            for (int n = 0; n < 8; n++)
                #pragma unroll
                for (int q = 0; q < 4; q++) d[s][n][q] = 0.f;

        #pragma unroll
        for (int k2 = 0; k2 < 4; k2++){
            const int hA = 2*t + 16*k2;
            float2 bA = *(const float2*)&sbase[e][hA];
            float2 dA = *(const float2*)&sdel[hA];
            float2 bB = *(const float2*)&sbase[e][hA+8];
            float2 dB = *(const float2*)&sdel[hA+8];

            uint32_t aH[2][4];
            #pragma unroll
            for (int s = 0; s < 2; s++){
                float cf = (float)(cb + 16*s + g);
                aH[s][0] = packh2(__sinf(fmaf(cf,     dA.x, bA.x)),
                                  __sinf(fmaf(cf,     dA.y, bA.y)));
                aH[s][1] = packh2(__sinf(fmaf(cf+8.f, dA.x, bA.x)),
                                  __sinf(fmaf(cf+8.f, dA.y, bA.y)));
                aH[s][2] = packh2(__sinf(fmaf(cf,     dB.x, bB.x)),
                                  __sinf(fmaf(cf,     dB.y, bB.y)));
                aH[s][3] = packh2(__sinf(fmaf(cf+8.f, dB.x, bB.x)),
                                  __sinf(fmaf(cf+8.f, dB.y, bB.y)));
            }
            uint32_t lma = lm_base + (uint32_t)(k2*8)*256u;
            #pragma unroll
            for (int nt = 0; nt < 8; nt++){
                uint32_t r0, r1;
                asm volatile("ldmatrix.sync.aligned.m8n8.x2.trans.shared.b16 "
                             "{%0,%1}, [%2];"
                             : "=r"(r0), "=r"(r1) : "r"(lma));
                lma += 256u;
                mma16816(d[0][nt], aH[0], r0, r1);
                mma16816(d[1][nt], aH[1], r0, r1);
            }
        }

        // ---- epilogue ----
        int eg = 2*tile + e;
        bool val = (eg < Etot);
        float m00 = 0.f, m01 = 0.f, m10 = 0.f, m11 = 0.f;
        #pragma unroll
        for (int nt = 0; nt < 8; nt++){
            int col = 2*t + 8*nt;
            float2 bv = *(const float2*)&sb1[col];
            float2 yv = val ? *(const float2*)&g_Y[eg*YST + col] : make_float2(0.f, 0.f);
            m00 += __sinf(d[0][nt][0]+bv.x)*yv.x + __sinf(d[0][nt][1]+bv.y)*yv.y;
            m01 += __sinf(d[0][nt][2]+bv.x)*yv.x + __sinf(d[0][nt][3]+bv.y)*yv.y;
            m10 += __sinf(d[1][nt][0]+bv.x)*yv.x + __sinf(d[1][nt][1]+bv.y)*yv.y;
            m11 += __sinf(d[1][nt][2]+bv.x)*yv.x + __sinf(d[1][nt][3]+bv.y)*yv.y;
        }
        m00 += __shfl_xor_sync(~0u, m00, 1); m00 += __shfl_xor_sync(~0u, m00, 2);
        m01 += __shfl_xor_sync(~0u, m01, 1); m01 += __shfl_xor_sync(~0u, m01, 2);
        m10 += __shfl_xor_sync(~0u, m10, 1); m10 += __shfl_xor_sync(~0u, m10, 2);
        m11 += __shfl_xor_sync(~0u, m11, 1); m11 += __shfl_xor_sync(~0u, m11, 2);
        if (t == 0 && val){
            int dst = g_dst[eg];
            float eb = g_Y[eg*YST + 64];
            atomicAdd(&acc[dst*HD + cb + g     ], m00 + eb);
            atomicAdd(&acc[dst*HD + cb + g + 8 ], m01 + eb);
            atomicAdd(&acc[dst*HD + cb + g + 16], m10 + eb);
            atomicAdd(&acc[dst*HD + cb + g + 24], m11 + eb);
        }
    }
}

// ---------------- post (h1 + pool self-init) ----------------
__global__ void k_post0(const float* __restrict__ acc, const float* __restrict__ bias){
    int i = blockIdx.x*blockDim.x + threadIdx.x;
    float v = sinf(OMEGA_ENC*(acc[i] + bias[i & 63]));
    g_h1[i] = v;
    g_pool[i] = (__float_as_uint(v) == 0x80000000u) ? 0.f : v;  // canonicalize -0
}
__global__ void k_post(const float* __restrict__ acc, const float* __restrict__ bias,
                       float* __restrict__ out, int n){
    int i = blockIdx.x*blockDim.x + threadIdx.x;
    if (i < n) out[i] = sinf(OMEGA_ENC*(acc[i] + bias[i & 63]));
}
__device__ __forceinline__ void atomicMaxF(float* addr, float v){
    if (__float_as_uint(v) == 0x80000000u) v = 0.f;
    if (v >= 0.f) atomicMax((int*)addr, __float_as_int(v));
    else          atomicMin((unsigned int*)addr, __float_as_uint(v));
}
__global__ void k_pool(int E){      // real edges only; self handled by k_post0
    int idx = blockIdx.x*blockDim.x + threadIdx.x;
    int e = idx >> 6, c = idx & 63;
    if (e >= E) return;
    atomicMaxF(&g_pool[g_dst[e]*HD + c], g_h1[g_src[e]*HD + c]);
}
__global__ void k_xf1(const int* __restrict__ keep, const float* __restrict__ pos1){
    int j = blockIdx.x, t = threadIdx.x;
    if (t < HD){
        g_xf1[j*SXF+t] = g_pool[keep[j]*HD + t];
        g_acc1[j*HD+t] = 0.f;
    } else if (t < HD+3) g_xf1[j*SXF+t] = pos1[j*3 + (t - HD)];
}
__global__ void k_final(const float* __restrict__ w, const float* __restrict__ b,
                        float* __restrict__ out){
    int j = blockIdx.x, l = threadIdx.x;
    float s = b[l];
    #pragma unroll
    for (int c = 0; c < HD; c++) s += g_h2[j*HD+c]*w[c*LATD+l];
    out[j*LATD+l] = sinf(OMEGA_ENC*s);
}

// ---------------- launch ----------------
extern "C" void kernel_launch(void* const* d_in, const int* in_sizes, int n_in,
                              void* d_out, int out_size){
    int iPos = 1, iEi = 2;
    if (in_sizes[1] == in_sizes[0]) { iEi = 1; iPos = 2; }

    const float* x      = (const float*)d_in[0];
    const float* pos    = (const float*)d_in[iPos];
    const int*   ei     = (const int*)  d_in[iEi];
    const int*   ei1    = (const int*)  d_in[3];
    const float* pos1   = (const float*)d_in[4];
    const int*   keep   = (const int*)  d_in[5];
    const float* lin0_w = (const float*)d_in[6];
    const float* lin0_b = (const float*)d_in[7];
    const float* lin1_w = (const float*)d_in[8];
    const float* lin1_b = (const float*)d_in[9];
    const float* c0p[7]; for (int i = 0; i < 7; i++) c0p[i] = (const float*)d_in[10+i];
    const float* c1p[7]; for (int i = 0; i < 7; i++) c1p[i] = (const float*)d_in[17+i];

    int N0 = in_sizes[0] / 8;
    int E0 = in_sizes[iEi] / 2;
    int N1 = in_sizes[5];
    int E1 = in_sizes[3] / 2;
    int Et0 = E0 + N0, Et1 = E1 + N1;
    int nt0 = (Et0 + 1)/2, nt1 = (Et1 + 1)/2;
    float* out = (float*)d_out;

    float *xf0, *acc0, *xf1, *acc1, *h2, *w2p;
    __half* bt;
    cudaGetSymbolAddress((void**)&xf0,  g_xf0);
    cudaGetSymbolAddress((void**)&acc0, g_acc0);
    cudaGetSymbolAddress((void**)&xf1,  g_xf1);
    cudaGetSymbolAddress((void**)&acc1, g_acc1);
    cudaGetSymbolAddress((void**)&h2,   g_h2);
    cudaGetSymbolAddress((void**)&bt,   g_Bt);
    cudaGetSymbolAddress((void**)&w2p,  g_w2p);

    int g0 = nt0 < 592 ? nt0 : 592;
    int g1 = nt1 < 592 ? nt1 : 592;

    k_prepB <<<32, 256>>>(c0p[2], c1p[2]);
    k_prepW2<<<(2*W2R*SXF + 255)/256, 256>>>(c0p[4], c1p[4], c0p[5], c1p[5]);
    k_enc   <<<N0, HD>>>(x, pos, lin0_w, lin0_b);

    // ---- conv0 ----
    k_prepEY<<<(Et0*YST + 255)/256, 256>>>(ei, E0, Et0, pos, xf0, w2p);
    k_convTC<<<g0, 128>>>(c0p[0], c0p[1], c0p[3], bt, Et0, nt0, acc0);
    k_post0 <<<(N0*HD)/256, 256>>>(acc0, c0p[6]);

    // ---- pool ----
    k_pool<<<(E0*HD + 255)/256, 256>>>(E0);
    k_xf1 <<<N1, 96>>>(keep, pos1);

    // ---- conv1 ----
    k_prepEY<<<(Et1*YST + 255)/256, 256>>>(ei1, E1, Et1, pos1, xf1, w2p + W2R*SXF);
    k_convTC<<<g1, 128>>>(c1p[0], c1p[1], c1p[3], bt + 4096, Et1, nt1, acc1);
    k_post  <<<(N1*HD + 255)/256, 256>>>(acc1, c1p[6], h2, N1*HD);

    k_final<<<N1, LATD>>>(lin1_w, lin1_b, out);
}

// round 10
// speedup vs baseline: 3.8272x; 1.2956x over previous
#include <cuda_runtime.h>
#include <cuda_fp16.h>
#include <cstdint>

#define OMEGA_ENC 0.01f
#define HD   64
#define LATD 32
#define SXF  68          // padded xf row stride
#define YST  72          // Ynode row stride: cols 0-63 = y_k, col 64 = edb
#define W2R  72          // padded w2 rows: 0-63 = w2, 64 = b2, 65-71 = 0
#define N0MAX 4096
#define N1MAX 1024
#define ETMAX (16384 + 4096)

// ---------------- scratch ----------------
__device__ float  g_xf0[N0MAX*SXF];
__device__ float  g_xf1[N1MAX*SXF];
__device__ float  g_acc0[N0MAX*HD];
__device__ float  g_acc1[N1MAX*HD];
__device__ float  g_h1[N0MAX*HD];
__device__ float  g_pool[N0MAX*HD];
__device__ float  g_h2[N1MAX*HD];
__device__ float4 g_feat[ETMAX];
__device__ int    g_src[ETMAX];
__device__ int    g_dst[ETMAX];
__device__ float  g_Yn[N0MAX*YST];      // per-NODE Y (and b2-dot at col 64)
__device__ __half g_Bt[2][4096];        // fp16(0.1*w1), ldmatrix 8x8 tile layout
__device__ float  g_w2p[2][W2R*SXF];

// ---------------- helpers ----------------
__device__ __forceinline__ uint32_t smem_u32(const void* p){
    uint32_t a;
    asm("{ .reg .u64 t; cvta.to.shared.u64 t, %1; cvt.u32.u64 %0, t; }" : "=r"(a) : "l"(p));
    return a;
}
__device__ __forceinline__ uint32_t packh2(float v0, float v1){
    __half2 h = __floats2half2_rn(v0, v1);
    return *reinterpret_cast<uint32_t*>(&h);
}
__device__ __forceinline__ void mma16816(float* d, const uint32_t* a, uint32_t b0, uint32_t b1){
    asm volatile("mma.sync.aligned.m16n8k16.row.col.f32.f16.f16.f32 "
        "{%0,%1,%2,%3}, {%4,%5,%6,%7}, {%8,%9}, {%0,%1,%2,%3};"
        : "+f"(d[0]), "+f"(d[1]), "+f"(d[2]), "+f"(d[3])
        : "r"(a[0]), "r"(a[1]), "r"(a[2]), "r"(a[3]), "r"(b0), "r"(b1));
}

// ---------------- prep: B tiles (fp16 of 0.1*w1, 8x8 tile layout) --------------
__global__ void k_prepB(const float* __restrict__ w1a, const float* __restrict__ w1b){
    int i = blockIdx.x*blockDim.x + threadIdx.x;
    if (i >= 2*4096) return;
    int conv = i >> 12, j = i & 4095;
    int group = j >> 6, rc = j & 63;
    int kh = group & 1, gnt = group >> 1;
    int k2 = gnt >> 3, nt = gnt & 7;
    int r = rc >> 3, c = rc & 7;
    int h = k2*16 + kh*8 + r;
    int n = nt*8 + c;
    const float* w1 = conv ? w1b : w1a;
    g_Bt[conv][j] = __float2half_rn(0.1f * w1[h*HD + n]);
}

// ---------------- prep: padded w2 (row 64 = b2) ----------------
__global__ void k_prepW2(const float* __restrict__ w2a, const float* __restrict__ w2b,
                         const float* __restrict__ b2a, const float* __restrict__ b2b){
    int i = blockIdx.x*blockDim.x + threadIdx.x;
    if (i >= 2*W2R*SXF) return;
    int conv = i / (W2R*SXF), j = i % (W2R*SXF);
    int k = j / SXF, f = j % SXF;
    const float* w2 = conv ? w2b : w2a;
    const float* b2 = conv ? b2b : b2a;
    float v = 0.f;
    if (f < 67){
        if (k < 64) v = w2[k*67 + f];
        else if (k == 64) v = b2[f];
    }
    g_w2p[conv][j] = v;
}

// ---------------- encoder (+acc0 init) ----------------
__global__ void k_enc(const float* __restrict__ x, const float* __restrict__ pos,
                      const float* __restrict__ w, const float* __restrict__ b){
    int i = blockIdx.x; int t = threadIdx.x;
    float s = b[t];
    #pragma unroll
    for (int f = 0; f < 8; f++) s += x[i*8+f]*w[f*HD+t];
    g_xf0[i*SXF+t] = sinf(OMEGA_ENC*s);
    if (t < 3) g_xf0[i*SXF+HD+t] = pos[i*3+t];
    g_acc0[i*HD+t] = 0.f;
}

// ---------------- fused prep: per-NODE Y + per-edge geometry ----------------
// idx < N*YST: thread (n, k) computes Ynode[n,k] = w2p[k,:].xf[n]  (k<=64)
// idx >= N*YST: eg = idx - N*YST does edge geometry -> feat/src/dst
__global__ void k_prep(const int* __restrict__ ei, int E, int Etot, int N,
                       const float* __restrict__ pos, const float* __restrict__ xf,
                       const float* __restrict__ w2p){
    int idx = blockIdx.x*blockDim.x + threadIdx.x;
    int nwork = N*YST;
    if (idx < nwork){
        int n = idx / YST, k = idx - n*YST;
        if (k > 64) return;
        const float4* xr = (const float4*)(xf + n*SXF);
        const float4* wr = (const float4*)(w2p + k*SXF);
        float y = 0.f;
        #pragma unroll
        for (int i = 0; i < 17; i++){
            float4 a = xr[i], b = wr[i];
            y += a.x*b.x + a.y*b.y + a.z*b.z + a.w*b.w;
        }
        g_Yn[n*YST + k] = y;
    } else {
        int eg = idx - nwork;
        if (eg >= Etot) return;
        int src, dst;
        float f0 = 0.f, f1 = 0.f, f2 = 0.f;
        if (eg < E){
            src = ei[eg]; dst = ei[E+eg];
            float rx = pos[dst*3+0]-pos[src*3+0];
            float ry = pos[dst*3+1]-pos[src*3+1];
            float rz = pos[dst*3+2]-pos[src*3+2];
            if (!(rx == 0.f && ry == 0.f && rz == 0.f)){
                float rho = sqrtf(rx*rx+ry*ry+rz*rz);
                float th  = atan2f(ry, rx);
                float ratio = fminf(fmaxf(rz/rho, -1.f), 1.f);
                float ph  = asinf(ratio);
                const float inv_pi = 0.3183098861837907f;
                f0 = rho; f1 = th*inv_pi; f2 = ph*inv_pi;
            }
        } else { src = eg - E; dst = src; }
        g_feat[eg] = make_float4(f0, f1, f2, 0.f);
        g_src[eg] = src; g_dst[eg] = dst;
    }
}

// ---------------- HMMA kernel conv (single-term fp16) ----------------
__global__ __launch_bounds__(128, 4) void k_convTC(
    const float* __restrict__ w0, const float* __restrict__ b0,
    const float* __restrict__ b1, const __half* __restrict__ Bt,
    int Etot, int ntiles, float* __restrict__ acc)
{
    __shared__ __align__(16) __half smB[4096];
    __shared__ float sbase[2][64];
    __shared__ float sdel[64];
    __shared__ float sb1[64];

    const int tid = threadIdx.x;
    {
        const uint4* s = (const uint4*)Bt;
        uint4* d = (uint4*)smB;
        #pragma unroll
        for (int i = 0; i < 4; i++) d[tid + 128*i] = s[tid + 128*i];
    }
    if (tid < 64){ sdel[tid] = 0.1f*w0[192+tid]; sb1[tid] = 0.1f*b1[tid]; }

    const int hb = tid & 63;
    const float w0a = w0[hb], w0b_ = w0[64+hb], w0c = w0[128+hb], b0h = b0[hb];

    const int w = tid >> 5, l = tid & 31, g = l >> 2, t = l & 3;
    const int e  = w >> 1;
    const int cb = 32*(w & 1);
    const int e2 = tid >> 6;
    const uint32_t lm_base = smem_u32(smB) +
        (uint32_t)(((((l >> 3) & 1)*64) + (l & 7)*8) * 2);

    __syncthreads();

    for (int tile = blockIdx.x; tile < ntiles; tile += gridDim.x){
        __syncthreads();
        {   // base generation: thread (e2 = tid>>6, hb)
            int eg = 2*tile + e2;
            float4 ft = (eg < Etot) ? g_feat[eg] : make_float4(0.f,0.f,0.f,0.f);
            sbase[e2][hb] = 0.1f*(ft.x*w0a + ft.y*w0b_ + ft.z*w0c + b0h);
        }
        __syncthreads();

        float d[2][8][4];
        #pragma unroll
        for (int s = 0; s < 2; s++)
            #pragma unroll
            for (int n = 0; n < 8; n++)
                #pragma unroll
                for (int q = 0; q < 4; q++) d[s][n][q] = 0.f;

        #pragma unroll
        for (int k2 = 0; k2 < 4; k2++){
            const int hA = 2*t + 16*k2;
            float2 bA = *(const float2*)&sbase[e][hA];
            float2 dA = *(const float2*)&sdel[hA];
            float2 bB = *(const float2*)&sbase[e][hA+8];
            float2 dB = *(const float2*)&sdel[hA+8];

            uint32_t aH[2][4];
            #pragma unroll
            for (int s = 0; s < 2; s++){
                float cf = (float)(cb + 16*s + g);
                aH[s][0] = packh2(__sinf(fmaf(cf,     dA.x, bA.x)),
                                  __sinf(fmaf(cf,     dA.y, bA.y)));
                aH[s][1] = packh2(__sinf(fmaf(cf+8.f, dA.x, bA.x)),
                                  __sinf(fmaf(cf+8.f, dA.y, bA.y)));
                aH[s][2] = packh2(__sinf(fmaf(cf,     dB.x, bB.x)),
                                  __sinf(fmaf(cf,     dB.y, bB.y)));
                aH[s][3] = packh2(__sinf(fmaf(cf+8.f, dB.x, bB.x)),
                                  __sinf(fmaf(cf+8.f, dB.y, bB.y)));
            }
            uint32_t lma = lm_base + (uint32_t)(k2*8)*256u;
            #pragma unroll
            for (int nt = 0; nt < 8; nt++){
                uint32_t r0, r1;
                asm volatile("ldmatrix.sync.aligned.m8n8.x2.trans.shared.b16 "
                             "{%0,%1}, [%2];"
                             : "=r"(r0), "=r"(r1) : "r"(lma));
                lma += 256u;
                mma16816(d[0][nt], aH[0], r0, r1);
                mma16816(d[1][nt], aH[1], r0, r1);
            }
        }

        // ---- epilogue: Y gathered per-node via src ----
        int eg = 2*tile + e;
        bool val = (eg < Etot);
        int sn = val ? g_src[eg] : 0;
        const float* yrow = &g_Yn[sn*YST];
        float m00 = 0.f, m01 = 0.f, m10 = 0.f, m11 = 0.f;
        #pragma unroll
        for (int nt = 0; nt < 8; nt++){
            int col = 2*t + 8*nt;
            float2 bv = *(const float2*)&sb1[col];
            float2 yv = val ? *(const float2*)&yrow[col] : make_float2(0.f, 0.f);
            m00 += __sinf(d[0][nt][0]+bv.x)*yv.x + __sinf(d[0][nt][1]+bv.y)*yv.y;
            m01 += __sinf(d[0][nt][2]+bv.x)*yv.x + __sinf(d[0][nt][3]+bv.y)*yv.y;
            m10 += __sinf(d[1][nt][0]+bv.x)*yv.x + __sinf(d[1][nt][1]+bv.y)*yv.y;
            m11 += __sinf(d[1][nt][2]+bv.x)*yv.x + __sinf(d[1][nt][3]+bv.y)*yv.y;
        }
        m00 += __shfl_xor_sync(~0u, m00, 1); m00 += __shfl_xor_sync(~0u, m00, 2);
        m01 += __shfl_xor_sync(~0u, m01, 1); m01 += __shfl_xor_sync(~0u, m01, 2);
        m10 += __shfl_xor_sync(~0u, m10, 1); m10 += __shfl_xor_sync(~0u, m10, 2);
        m11 += __shfl_xor_sync(~0u, m11, 1); m11 += __shfl_xor_sync(~0u, m11, 2);
        if (t == 0 && val){
            int dst = g_dst[eg];
            float eb = yrow[64];
            atomicAdd(&acc[dst*HD + cb + g     ], m00 + eb);
            atomicAdd(&acc[dst*HD + cb + g + 8 ], m01 + eb);
            atomicAdd(&acc[dst*HD + cb + g + 16], m10 + eb);
            atomicAdd(&acc[dst*HD + cb + g + 24], m11 + eb);
        }
    }
}

// ---------------- post (h1 + pool self-init) ----------------
__global__ void k_post0(const float* __restrict__ acc, const float* __restrict__ bias){
    int i = blockIdx.x*blockDim.x + threadIdx.x;
    float v = sinf(OMEGA_ENC*(acc[i] + bias[i & 63]));
    g_h1[i] = v;
    g_pool[i] = (__float_as_uint(v) == 0x80000000u) ? 0.f : v;  // canonicalize -0
}
__global__ void k_post(const float* __restrict__ acc, const float* __restrict__ bias,
                       float* __restrict__ out, int n){
    int i = blockIdx.x*blockDim.x + threadIdx.x;
    if (i < n) out[i] = sinf(OMEGA_ENC*(acc[i] + bias[i & 63]));
}
__device__ __forceinline__ void atomicMaxF(float* addr, float v){
    if (__float_as_uint(v) == 0x80000000u) v = 0.f;
    if (v >= 0.f) atomicMax((int*)addr, __float_as_int(v));
    else          atomicMin((unsigned int*)addr, __float_as_uint(v));
}
__global__ void k_pool(int E){      // real edges only; self handled by k_post0
    int idx = blockIdx.x*blockDim.x + threadIdx.x;
    int e = idx >> 6, c = idx & 63;
    if (e >= E) return;
    atomicMaxF(&g_pool[g_dst[e]*HD + c], g_h1[g_src[e]*HD + c]);
}
__global__ void k_xf1(const int* __restrict__ keep, const float* __restrict__ pos1){
    int j = blockIdx.x, t = threadIdx.x;
    if (t < HD){
        g_xf1[j*SXF+t] = g_pool[keep[j]*HD + t];
        g_acc1[j*HD+t] = 0.f;
    } else if (t < HD+3) g_xf1[j*SXF+t] = pos1[j*3 + (t - HD)];
}
__global__ void k_final(const float* __restrict__ w, const float* __restrict__ b,
                        float* __restrict__ out){
    int j = blockIdx.x, l = threadIdx.x;
    float s = b[l];
    #pragma unroll
    for (int c = 0; c < HD; c++) s += g_h2[j*HD+c]*w[c*LATD+l];
    out[j*LATD+l] = sinf(OMEGA_ENC*s);
}

// ---------------- launch ----------------
extern "C" void kernel_launch(void* const* d_in, const int* in_sizes, int n_in,
                              void* d_out, int out_size){
    int iPos = 1, iEi = 2;
    if (in_sizes[1] == in_sizes[0]) { iEi = 1; iPos = 2; }

    const float* x      = (const float*)d_in[0];
    const float* pos    = (const float*)d_in[iPos];
    const int*   ei     = (const int*)  d_in[iEi];
    const int*   ei1    = (const int*)  d_in[3];
    const float* pos1   = (const float*)d_in[4];
    const int*   keep   = (const int*)  d_in[5];
    const float* lin0_w = (const float*)d_in[6];
    const float* lin0_b = (const float*)d_in[7];
    const float* lin1_w = (const float*)d_in[8];
    const float* lin1_b = (const float*)d_in[9];
    const float* c0p[7]; for (int i = 0; i < 7; i++) c0p[i] = (const float*)d_in[10+i];
    const float* c1p[7]; for (int i = 0; i < 7; i++) c1p[i] = (const float*)d_in[17+i];

    int N0 = in_sizes[0] / 8;
    int E0 = in_sizes[iEi] / 2;
    int N1 = in_sizes[5];
    int E1 = in_sizes[3] / 2;
    int Et0 = E0 + N0, Et1 = E1 + N1;
    int nt0 = (Et0 + 1)/2, nt1 = (Et1 + 1)/2;
    float* out = (float*)d_out;

    float *xf0, *acc0, *xf1, *acc1, *h2, *w2p;
    __half* bt;
    cudaGetSymbolAddress((void**)&xf0,  g_xf0);
    cudaGetSymbolAddress((void**)&acc0, g_acc0);
    cudaGetSymbolAddress((void**)&xf1,  g_xf1);
    cudaGetSymbolAddress((void**)&acc1, g_acc1);
    cudaGetSymbolAddress((void**)&h2,   g_h2);
    cudaGetSymbolAddress((void**)&bt,   g_Bt);
    cudaGetSymbolAddress((void**)&w2p,  g_w2p);

    int g0 = nt0 < 592 ? nt0 : 592;
    int g1 = nt1 < 592 ? nt1 : 592;

    k_prepB <<<32, 256>>>(c0p[2], c1p[2]);
    k_prepW2<<<(2*W2R*SXF + 255)/256, 256>>>(c0p[4], c1p[4], c0p[5], c1p[5]);
    k_enc   <<<N0, HD>>>(x, pos, lin0_w, lin0_b);

    // ---- conv0 ----
    k_prep  <<<(N0*YST + Et0 + 255)/256, 256>>>(ei, E0, Et0, N0, pos, xf0, w2p);
    k_convTC<<<g0, 128>>>(c0p[0], c0p[1], c0p[3], bt, Et0, nt0, acc0);
    k_post0 <<<(N0*HD)/256, 256>>>(acc0, c0p[6]);

    // ---- pool ----
    k_pool<<<(E0*HD + 255)/256, 256>>>(E0);
    k_xf1 <<<N1, 96>>>(keep, pos1);

    // ---- conv1 ----
    k_prep  <<<(N1*YST + Et1 + 255)/256, 256>>>(ei1, E1, Et1, N1, pos1, xf1, w2p + W2R*SXF);
    k_convTC<<<g1, 128>>>(c1p[0], c1p[1], c1p[3], bt + 4096, Et1, nt1, acc1);
    k_post  <<<(N1*HD + 255)/256, 256>>>(acc1, c1p[6], h2, N1*HD);

    k_final<<<N1, LATD>>>(lin1_w, lin1_b, out);
}

// round 11
// speedup vs baseline: 3.8325x; 1.0014x over previous
#include <cuda_runtime.h>
#include <cuda_fp16.h>
#include <cstdint>

#define OMEGA_ENC 0.01f
#define HD   64
#define LATD 32
#define SXF  68          // padded xf row stride (smem only now)
#define YST  72          // Ynode row stride: cols 0-63 = y_k, col 64 = edb
#define W2R  72          // padded w2 rows: 0-63 = w2, 64 = b2, 65-71 = 0
#define N0MAX 4096
#define N1MAX 1024
#define ETMAX (20480 + 10240)   // conv0 edges (off 0) + conv1 edges (off Et0)

// ---------------- scratch ----------------
__device__ float  g_acc0[N0MAX*HD];
__device__ float  g_acc1[N1MAX*HD];
__device__ float  g_h1[N0MAX*HD];
__device__ float  g_pool[N0MAX*HD];
__device__ float  g_h2[N1MAX*HD];
__device__ float4 g_feat[ETMAX];
__device__ int    g_src[ETMAX];
__device__ int    g_dst[ETMAX];
__device__ float  g_Yn[N0MAX*YST];      // per-NODE Y (col 64 = b2-dot); reused by conv1
__device__ __half g_Bt[2][4096];        // fp16(0.1*w1), ldmatrix 8x8 tile layout
__device__ float  g_w2p[2][W2R*SXF];

// ---------------- helpers ----------------
__device__ __forceinline__ uint32_t smem_u32(const void* p){
    uint32_t a;
    asm("{ .reg .u64 t; cvta.to.shared.u64 t, %1; cvt.u32.u64 %0, t; }" : "=r"(a) : "l"(p));
    return a;
}
__device__ __forceinline__ uint32_t packh2(float v0, float v1){
    __half2 h = __floats2half2_rn(v0, v1);
    return *reinterpret_cast<uint32_t*>(&h);
}
__device__ __forceinline__ void mma16816(float* d, const uint32_t* a, uint32_t b0, uint32_t b1){
    asm volatile("mma.sync.aligned.m16n8k16.row.col.f32.f16.f16.f32 "
        "{%0,%1,%2,%3}, {%4,%5,%6,%7}, {%8,%9}, {%0,%1,%2,%3};"
        : "+f"(d[0]), "+f"(d[1]), "+f"(d[2]), "+f"(d[3])
        : "r"(a[0]), "r"(a[1]), "r"(a[2]), "r"(a[3]), "r"(b0), "r"(b1));
}

// ---------------- prep: B tiles (fp16 of 0.1*w1, 8x8 tile layout) --------------
__global__ void k_prepB(const float* __restrict__ w1a, const float* __restrict__ w1b){
    int i = blockIdx.x*blockDim.x + threadIdx.x;
    if (i >= 2*4096) return;
    int conv = i >> 12, j = i & 4095;
    int group = j >> 6, rc = j & 63;
    int kh = group & 1, gnt = group >> 1;
    int k2 = gnt >> 3, nt = gnt & 7;
    int r = rc >> 3, c = rc & 7;
    int h = k2*16 + kh*8 + r;
    int n = nt*8 + c;
    const float* w1 = conv ? w1b : w1a;
    g_Bt[conv][j] = __float2half_rn(0.1f * w1[h*HD + n]);
}

// ---------------- prep: padded w2 (row 64 = b2) ----------------
__global__ void k_prepW2(const float* __restrict__ w2a, const float* __restrict__ w2b,
                         const float* __restrict__ b2a, const float* __restrict__ b2b){
    int i = blockIdx.x*blockDim.x + threadIdx.x;
    if (i >= 2*W2R*SXF) return;
    int conv = i / (W2R*SXF), j = i % (W2R*SXF);
    int k = j / SXF, f = j % SXF;
    const float* w2 = conv ? w2b : w2a;
    const float* b2 = conv ? b2b : b2a;
    float v = 0.f;
    if (f < 67){
        if (k < 64) v = w2[k*67 + f];
        else if (k == 64) v = b2[f];
    }
    g_w2p[conv][j] = v;
}

// ---------------- edge geometry (independent of features) ----------------
__global__ void k_geo(const int* __restrict__ ei, int E, int Etot,
                      const float* __restrict__ pos, int off){
    int eg = blockIdx.x*blockDim.x + threadIdx.x;
    if (eg >= Etot) return;
    int src, dst;
    float f0 = 0.f, f1 = 0.f, f2 = 0.f;
    if (eg < E){
        src = ei[eg]; dst = ei[E+eg];
        float rx = pos[dst*3+0]-pos[src*3+0];
        float ry = pos[dst*3+1]-pos[src*3+1];
        float rz = pos[dst*3+2]-pos[src*3+2];
        if (!(rx == 0.f && ry == 0.f && rz == 0.f)){
            float rho = sqrtf(rx*rx+ry*ry+rz*rz);
            float th  = atan2f(ry, rx);
            float ratio = fminf(fmaxf(rz/rho, -1.f), 1.f);
            float ph  = asinf(ratio);
            const float inv_pi = 0.3183098861837907f;
            f0 = rho; f1 = th*inv_pi; f2 = ph*inv_pi;
        }
    } else { src = eg - E; dst = src; }
    g_feat[off+eg] = make_float4(f0, f1, f2, 0.f);
    g_src[off+eg] = src; g_dst[off+eg] = dst;
}

// ---------------- encoder fused with per-node Y (+acc0 init) ----------------
__global__ __launch_bounds__(128) void k_encY(
    const float* __restrict__ x, const float* __restrict__ pos,
    const float* __restrict__ w, const float* __restrict__ b,
    const float* __restrict__ w2p){
    __shared__ __align__(16) float xs[SXF];
    int i = blockIdx.x, t = threadIdx.x;
    if (t < 64){
        float s = b[t];
        #pragma unroll
        for (int f = 0; f < 8; f++) s += x[i*8+f]*w[f*HD+t];
        xs[t] = sinf(OMEGA_ENC*s);
        g_acc0[i*HD+t] = 0.f;
    } else if (t < 67) xs[t] = pos[i*3 + (t-64)];
    else if (t == 67) xs[67] = 0.f;
    __syncthreads();
    if (t < 65){
        const float4* xr = (const float4*)xs;
        const float4* wr = (const float4*)(w2p + t*SXF);
        float y = 0.f;
        #pragma unroll
        for (int q = 0; q < 17; q++){
            float4 a = xr[q], bb = wr[q];
            y += a.x*bb.x + a.y*bb.y + a.z*bb.z + a.w*bb.w;
        }
        g_Yn[i*YST + t] = y;
    }
}

// ---------------- pooled gather fused with per-node Y (+acc1 init) ----------------
__global__ __launch_bounds__(128) void k_xf1Y(
    const int* __restrict__ keep, const float* __restrict__ pos1,
    const float* __restrict__ w2p){
    __shared__ __align__(16) float xs[SXF];
    int j = blockIdx.x, t = threadIdx.x;
    if (t < 64){
        xs[t] = g_pool[keep[j]*HD + t];
        g_acc1[j*HD+t] = 0.f;
    } else if (t < 67) xs[t] = pos1[j*3 + (t-64)];
    else if (t == 67) xs[67] = 0.f;
    __syncthreads();
    if (t < 65){
        const float4* xr = (const float4*)xs;
        const float4* wr = (const float4*)(w2p + t*SXF);
        float y = 0.f;
        #pragma unroll
        for (int q = 0; q < 17; q++){
            float4 a = xr[q], bb = wr[q];
            y += a.x*bb.x + a.y*bb.y + a.z*bb.z + a.w*bb.w;
        }
        g_Yn[j*YST + t] = y;
    }
}

// ---------------- HMMA kernel conv (single-term fp16, sync-free mainloop) -------
__global__ __launch_bounds__(128, 4) void k_convTC(
    const float* __restrict__ w0, const float* __restrict__ b0,
    const float* __restrict__ b1, const __half* __restrict__ Bt,
    int Etot, int ntiles, int off, float* __restrict__ acc)
{
    __shared__ __align__(16) __half smB[4096];
    __shared__ __align__(16) float4 sw4[64];   // 0.1*{w0a,w0b,w0c,b0} per h
    __shared__ __align__(8)  float sdel[64];
    __shared__ float sb1[64];

    const int tid = threadIdx.x;
    {
        const uint4* s = (const uint4*)Bt;
        uint4* d = (uint4*)smB;
        #pragma unroll
        for (int i = 0; i < 4; i++) d[tid + 128*i] = s[tid + 128*i];
    }
    if (tid < 64){
        sdel[tid] = 0.1f*w0[192+tid];
        sb1[tid]  = 0.1f*b1[tid];
        sw4[tid]  = make_float4(0.1f*w0[tid], 0.1f*w0[64+tid],
                                0.1f*w0[128+tid], 0.1f*b0[tid]);
    }

    const int w = tid >> 5, l = tid & 31, g = l >> 2, t = l & 3;
    const int e  = w >> 1;
    const int cb = 32*(w & 1);
    const uint32_t lm_base = smem_u32(smB) +
        (uint32_t)(((((l >> 3) & 1)*64) + (l & 7)*8) * 2);

    __syncthreads();   // only sync: smem tables ready

    for (int tile = blockIdx.x; tile < ntiles; tile += gridDim.x){
        int eg = 2*tile + e;
        bool val = (eg < Etot);
        float4 ft = val ? g_feat[off+eg] : make_float4(0.f,0.f,0.f,0.f);

        float d[2][8][4];
        #pragma unroll
        for (int s = 0; s < 2; s++)
            #pragma unroll
            for (int n = 0; n < 8; n++)
                #pragma unroll
                for (int q = 0; q < 4; q++) d[s][n][q] = 0.f;

        #pragma unroll
        for (int k2 = 0; k2 < 4; k2++){
            const int hA = 2*t + 16*k2;
            float4 s0 = sw4[hA],   s1 = sw4[hA+1];
            float4 s2 = sw4[hA+8], s3 = sw4[hA+9];
            float b0v = fmaf(ft.x, s0.x, fmaf(ft.y, s0.y, fmaf(ft.z, s0.z, s0.w)));
            float b1v = fmaf(ft.x, s1.x, fmaf(ft.y, s1.y, fmaf(ft.z, s1.z, s1.w)));
            float b2v = fmaf(ft.x, s2.x, fmaf(ft.y, s2.y, fmaf(ft.z, s2.z, s2.w)));
            float b3v = fmaf(ft.x, s3.x, fmaf(ft.y, s3.y, fmaf(ft.z, s3.z, s3.w)));
            float2 dA = *(const float2*)&sdel[hA];
            float2 dB = *(const float2*)&sdel[hA+8];

            uint32_t aH[2][4];
            #pragma unroll
            for (int s = 0; s < 2; s++){
                float cf = (float)(cb + 16*s + g);
                aH[s][0] = packh2(__sinf(fmaf(cf,     dA.x, b0v)),
                                  __sinf(fmaf(cf,     dA.y, b1v)));
                aH[s][1] = packh2(__sinf(fmaf(cf+8.f, dA.x, b0v)),
                                  __sinf(fmaf(cf+8.f, dA.y, b1v)));
                aH[s][2] = packh2(__sinf(fmaf(cf,     dB.x, b2v)),
                                  __sinf(fmaf(cf,     dB.y, b3v)));
                aH[s][3] = packh2(__sinf(fmaf(cf+8.f, dB.x, b2v)),
                                  __sinf(fmaf(cf+8.f, dB.y, b3v)));
            }
            uint32_t lma = lm_base + (uint32_t)(k2*8)*256u;
            #pragma unroll
            for (int nt = 0; nt < 8; nt++){
                uint32_t r0, r1;
                asm volatile("ldmatrix.sync.aligned.m8n8.x2.trans.shared.b16 "
                             "{%0,%1}, [%2];"
                             : "=r"(r0), "=r"(r1) : "r"(lma));
                lma += 256u;
                mma16816(d[0][nt], aH[0], r0, r1);
                mma16816(d[1][nt], aH[1], r0, r1);
            }
        }

        // ---- epilogue: Y gathered per-node via src ----
        int sn = val ? g_src[off+eg] : 0;
        const float* yrow = &g_Yn[sn*YST];
        float m00 = 0.f, m01 = 0.f, m10 = 0.f, m11 = 0.f;
        #pragma unroll
        for (int nt = 0; nt < 8; nt++){
            int col = 2*t + 8*nt;
            float2 bv = *(const float2*)&sb1[col];
            float2 yv = val ? *(const float2*)&yrow[col] : make_float2(0.f, 0.f);
            m00 += __sinf(d[0][nt][0]+bv.x)*yv.x + __sinf(d[0][nt][1]+bv.y)*yv.y;
            m01 += __sinf(d[0][nt][2]+bv.x)*yv.x + __sinf(d[0][nt][3]+bv.y)*yv.y;
            m10 += __sinf(d[1][nt][0]+bv.x)*yv.x + __sinf(d[1][nt][1]+bv.y)*yv.y;
            m11 += __sinf(d[1][nt][2]+bv.x)*yv.x + __sinf(d[1][nt][3]+bv.y)*yv.y;
        }
        m00 += __shfl_xor_sync(~0u, m00, 1); m00 += __shfl_xor_sync(~0u, m00, 2);
        m01 += __shfl_xor_sync(~0u, m01, 1); m01 += __shfl_xor_sync(~0u, m01, 2);
        m10 += __shfl_xor_sync(~0u, m10, 1); m10 += __shfl_xor_sync(~0u, m10, 2);
        m11 += __shfl_xor_sync(~0u, m11, 1); m11 += __shfl_xor_sync(~0u, m11, 2);
        if (t == 0 && val){
            int dst = g_dst[off+eg];
            float eb = yrow[64];
            atomicAdd(&acc[dst*HD + cb + g     ], m00 + eb);
            atomicAdd(&acc[dst*HD + cb + g + 8 ], m01 + eb);
            atomicAdd(&acc[dst*HD + cb + g + 16], m10 + eb);
            atomicAdd(&acc[dst*HD + cb + g + 24], m11 + eb);
        }
    }
}

// ---------------- post (h1 + pool self-init) ----------------
__global__ void k_post0(const float* __restrict__ acc, const float* __restrict__ bias){
    int i = blockIdx.x*blockDim.x + threadIdx.x;
    float v = sinf(OMEGA_ENC*(acc[i] + bias[i & 63]));
    g_h1[i] = v;
    g_pool[i] = (__float_as_uint(v) == 0x80000000u) ? 0.f : v;  // canonicalize -0
}
__global__ void k_post(const float* __restrict__ acc, const float* __restrict__ bias,
                       float* __restrict__ out, int n){
    int i = blockIdx.x*blockDim.x + threadIdx.x;
    if (i < n) out[i] = sinf(OMEGA_ENC*(acc[i] + bias[i & 63]));
}
__device__ __forceinline__ void atomicMaxF(float* addr, float v){
    if (__float_as_uint(v) == 0x80000000u) v = 0.f;
    if (v >= 0.f) atomicMax((int*)addr, __float_as_int(v));
    else          atomicMin((unsigned int*)addr, __float_as_uint(v));
}
__global__ void k_pool(int E){      // real edges only; self handled by k_post0
    int idx = blockIdx.x*blockDim.x + threadIdx.x;
    int e = idx >> 6, c = idx & 63;
    if (e >= E) return;
    atomicMaxF(&g_pool[g_dst[e]*HD + c], g_h1[g_src[e]*HD + c]);
}
__global__ void k_final(const float* __restrict__ w, const float* __restrict__ b,
                        float* __restrict__ out){
    int j = blockIdx.x, l = threadIdx.x;
    float s = b[l];
    #pragma unroll
    for (int c = 0; c < HD; c++) s += g_h2[j*HD+c]*w[c*LATD+l];
    out[j*LATD+l] = sinf(OMEGA_ENC*s);
}

// ---------------- launch ----------------
extern "C" void kernel_launch(void* const* d_in, const int* in_sizes, int n_in,
                              void* d_out, int out_size){
    int iPos = 1, iEi = 2;
    if (in_sizes[1] == in_sizes[0]) { iEi = 1; iPos = 2; }

    const float* x      = (const float*)d_in[0];
    const float* pos    = (const float*)d_in[iPos];
    const int*   ei     = (const int*)  d_in[iEi];
    const int*   ei1    = (const int*)  d_in[3];
    const float* pos1   = (const float*)d_in[4];
    const int*   keep   = (const int*)  d_in[5];
    const float* lin0_w = (const float*)d_in[6];
    const float* lin0_b = (const float*)d_in[7];
    const float* lin1_w = (const float*)d_in[8];
    const float* lin1_b = (const float*)d_in[9];
    const float* c0p[7]; for (int i = 0; i < 7; i++) c0p[i] = (const float*)d_in[10+i];
    const float* c1p[7]; for (int i = 0; i < 7; i++) c1p[i] = (const float*)d_in[17+i];

    int N0 = in_sizes[0] / 8;
    int E0 = in_sizes[iEi] / 2;
    int N1 = in_sizes[5];
    int E1 = in_sizes[3] / 2;
    int Et0 = E0 + N0, Et1 = E1 + N1;
    int nt0 = (Et0 + 1)/2, nt1 = (Et1 + 1)/2;
    float* out = (float*)d_out;

    float *acc0, *acc1, *h2, *w2p;
    __half* bt;
    cudaGetSymbolAddress((void**)&acc0, g_acc0);
    cudaGetSymbolAddress((void**)&acc1, g_acc1);
    cudaGetSymbolAddress((void**)&h2,   g_h2);
    cudaGetSymbolAddress((void**)&bt,   g_Bt);
    cudaGetSymbolAddress((void**)&w2p,  g_w2p);

    int g0 = nt0 < 592 ? nt0 : 592;
    int g1 = nt1 < 592 ? nt1 : 592;

    k_prepB <<<32, 256>>>(c0p[2], c1p[2]);
    k_prepW2<<<(2*W2R*SXF + 255)/256, 256>>>(c0p[4], c1p[4], c0p[5], c1p[5]);
    k_geo   <<<(Et0 + 127)/128, 128>>>(ei,  E0, Et0, pos,  0);
    k_geo   <<<(Et1 + 127)/128, 128>>>(ei1, E1, Et1, pos1, Et0);
    k_encY  <<<N0, 128>>>(x, pos, lin0_w, lin0_b, w2p);

    // ---- conv0 ----
    k_convTC<<<g0, 128>>>(c0p[0], c0p[1], c0p[3], bt, Et0, nt0, 0, acc0);
    k_post0 <<<(N0*HD)/256, 256>>>(acc0, c0p[6]);

    // ---- pool ----
    k_pool<<<(E0*HD + 255)/256, 256>>>(E0);
    k_xf1Y<<<N1, 128>>>(keep, pos1, w2p + W2R*SXF);

    // ---- conv1 ----
    k_convTC<<<g1, 128>>>(c1p[0], c1p[1], c1p[3], bt + 4096, Et1, nt1, Et0, acc1);
    k_post  <<<(N1*HD + 255)/256, 256>>>(acc1, c1p[6], h2, N1*HD);

    k_final<<<N1, LATD>>>(lin1_w, lin1_b, out);
}

// round 12
// speedup vs baseline: 3.8866x; 1.0141x over previous
#include <cuda_runtime.h>
#include <cuda_fp16.h>
#include <cstdint>

#define OMEGA_ENC 0.01f
#define HD   64
#define LATD 32
#define SXF  68          // padded xf row stride (smem only)
#define YST  72          // Ynode row stride: cols 0-63 = y_k, col 64 = edb
#define W2R  72          // padded w2 rows: 0-63 = w2, 64 = b2, 65-71 = 0
#define N0MAX 4096
#define N1MAX 1024
#define ETMAX (20480 + 10240)

// ---------------- scratch ----------------
__device__ float  g_acc0[N0MAX*HD];
__device__ float  g_acc1[N1MAX*HD];
__device__ float  g_h1[N0MAX*HD];
__device__ float  g_pool[N0MAX*HD];
__device__ float  g_h2[N1MAX*HD];
__device__ float4 g_feat[ETMAX];
__device__ int    g_src[ETMAX];
__device__ int    g_dst[ETMAX];
__device__ float  g_Yn[N0MAX*YST];
__device__ __half g_Bt[2][4096];
__device__ float  g_w2p[2][W2R*SXF];

// ---------------- helpers ----------------
__device__ __forceinline__ uint32_t smem_u32(const void* p){
    uint32_t a;
    asm("{ .reg .u64 t; cvta.to.shared.u64 t, %1; cvt.u32.u64 %0, t; }" : "=r"(a) : "l"(p));
    return a;
}
__device__ __forceinline__ uint32_t packh2(float v0, float v1){
    __half2 h = __floats2half2_rn(v0, v1);
    return *reinterpret_cast<uint32_t*>(&h);
}
__device__ __forceinline__ void mma16816(float* d, const uint32_t* a, uint32_t b0, uint32_t b1){
    asm volatile("mma.sync.aligned.m16n8k16.row.col.f32.f16.f16.f32 "
        "{%0,%1,%2,%3}, {%4,%5,%6,%7}, {%8,%9}, {%0,%1,%2,%3};"
        : "+f"(d[0]), "+f"(d[1]), "+f"(d[2]), "+f"(d[3])
        : "r"(a[0]), "r"(a[1]), "r"(a[2]), "r"(a[3]), "r"(b0), "r"(b1));
}

// ---------------- fused setup: prepB + prepW2 + geo(conv0) + geo(conv1) --------
__device__ __forceinline__ void geo_one(const int* ei, int E, int Etot,
                                        const float* pos, int off, int eg){
    if (eg >= Etot) return;
    int src, dst;
    float f0 = 0.f, f1 = 0.f, f2 = 0.f;
    if (eg < E){
        src = ei[eg]; dst = ei[E+eg];
        float rx = pos[dst*3+0]-pos[src*3+0];
        float ry = pos[dst*3+1]-pos[src*3+1];
        float rz = pos[dst*3+2]-pos[src*3+2];
        if (!(rx == 0.f && ry == 0.f && rz == 0.f)){
            float rho = sqrtf(rx*rx+ry*ry+rz*rz);
            float th  = atan2f(ry, rx);
            float ratio = fminf(fmaxf(rz/rho, -1.f), 1.f);
            float ph  = asinf(ratio);
            const float inv_pi = 0.3183098861837907f;
            f0 = rho; f1 = th*inv_pi; f2 = ph*inv_pi;
        }
    } else { src = eg - E; dst = src; }
    g_feat[off+eg] = make_float4(f0, f1, f2, 0.f);
    g_src[off+eg] = src; g_dst[off+eg] = dst;
}

__global__ void k_setup(
    const float* __restrict__ w1a, const float* __restrict__ w1b,
    const float* __restrict__ w2a, const float* __restrict__ w2b,
    const float* __restrict__ b2a, const float* __restrict__ b2b,
    const int* __restrict__ ei0, int E0, int Et0, const float* __restrict__ pos0,
    const int* __restrict__ ei1, int E1, int Et1, const float* __restrict__ pos1,
    int nbB, int nbBW, int nbBWG)
{
    int b = blockIdx.x, tid = threadIdx.x;
    if (b < nbB){                                   // ---- B tiles ----
        int i = b*256 + tid;
        int conv = i >> 12, j = i & 4095;
        int group = j >> 6, rc = j & 63;
        int kh = group & 1, gnt = group >> 1;
        int k2 = gnt >> 3, nt = gnt & 7;
        int r = rc >> 3, c = rc & 7;
        int h = k2*16 + kh*8 + r;
        int n = nt*8 + c;
        const float* w1 = conv ? w1b : w1a;
        g_Bt[conv][j] = __float2half_rn(0.1f * w1[h*HD + n]);
    } else if (b < nbBW){                           // ---- padded w2 ----
        int i = (b - nbB)*256 + tid;
        if (i >= 2*W2R*SXF) return;
        int conv = i / (W2R*SXF), j = i % (W2R*SXF);
        int k = j / SXF, f = j % SXF;
        const float* w2 = conv ? w2b : w2a;
        const float* b2 = conv ? b2b : b2a;
        float v = 0.f;
        if (f < 67){
            if (k < 64) v = w2[k*67 + f];
            else if (k == 64) v = b2[f];
        }
        g_w2p[conv][j] = v;
    } else if (b < nbBWG){                          // ---- geometry conv0 ----
        geo_one(ei0, E0, Et0, pos0, 0, (b - nbBW)*256 + tid);
    } else {                                        // ---- geometry conv1 ----
        geo_one(ei1, E1, Et1, pos1, Et0, (b - nbBWG)*256 + tid);
    }
}

// ---------------- encoder fused with per-node Y, 4 nodes/block -----------------
__global__ __launch_bounds__(256) void k_encY(
    const float* __restrict__ x, const float* __restrict__ pos,
    const float* __restrict__ w, const float* __restrict__ b,
    const float* __restrict__ w2p, int N){
    __shared__ __align__(16) float w2s[65*SXF];
    __shared__ __align__(16) float xs[4][SXF];
    int tid = threadIdx.x;
    for (int i = tid; i < 65*SXF; i += 256) w2s[i] = w2p[i];
    int node = tid >> 6, ch = tid & 63;
    int gn = blockIdx.x*4 + node;
    if (gn < N){
        float s = b[ch];
        #pragma unroll
        for (int f = 0; f < 8; f++) s += x[gn*8+f]*w[f*HD+ch];
        xs[node][ch] = sinf(OMEGA_ENC*s);
        g_acc0[gn*HD+ch] = 0.f;
        if (ch < 3) xs[node][HD+ch] = pos[gn*3+ch];
        if (ch == 3) xs[node][67] = 0.f;
    }
    __syncthreads();
    if (gn < N){
        const float4* xr = (const float4*)xs[node];
        const float4* wr = (const float4*)&w2s[ch*SXF];
        float y = 0.f;
        #pragma unroll
        for (int q = 0; q < 17; q++){
            float4 a = xr[q], bb = wr[q];
            y += a.x*bb.x + a.y*bb.y + a.z*bb.z + a.w*bb.w;
        }
        g_Yn[gn*YST + ch] = y;
        if (ch == 0){
            const float4* br = (const float4*)&w2s[64*SXF];
            float eb = 0.f;
            #pragma unroll
            for (int q = 0; q < 17; q++){
                float4 a = xr[q], bb = br[q];
                eb += a.x*bb.x + a.y*bb.y + a.z*bb.z + a.w*bb.w;
            }
            g_Yn[gn*YST + 64] = eb;
        }
    }
}

// ---------------- pooled gather fused with per-node Y (+acc1 init) -------------
__global__ __launch_bounds__(128) void k_xf1Y(
    const int* __restrict__ keep, const float* __restrict__ pos1,
    const float* __restrict__ w2p){
    __shared__ __align__(16) float xs[SXF];
    int j = blockIdx.x, t = threadIdx.x;
    if (t < 64){
        xs[t] = g_pool[keep[j]*HD + t];
        g_acc1[j*HD+t] = 0.f;
    } else if (t < 67) xs[t] = pos1[j*3 + (t-64)];
    else if (t == 67) xs[67] = 0.f;
    __syncthreads();
    if (t < 65){
        const float4* xr = (const float4*)xs;
        const float4* wr = (const float4*)(w2p + t*SXF);
        float y = 0.f;
        #pragma unroll
        for (int q = 0; q < 17; q++){
            float4 a = xr[q], bb = wr[q];
            y += a.x*bb.x + a.y*bb.y + a.z*bb.z + a.w*bb.w;
        }
        g_Yn[j*YST + t] = y;
    }
}

// ---------------- HMMA kernel conv (recurrence A-gen, single-term fp16) --------
__global__ __launch_bounds__(128, 4) void k_convTC(
    const float* __restrict__ w0, const float* __restrict__ b0,
    const float* __restrict__ b1, const __half* __restrict__ Bt,
    int Etot, int ntiles, int off, float* __restrict__ acc)
{
    __shared__ __align__(16) __half smB[4096];
    __shared__ __align__(16) float4 sw4[64];   // 0.1*{w0a,w0b,w0c,b0} per h
    __shared__ __align__(8)  float2 sc8[64];   // (cos(8*del), sin(8*del)) per h
    __shared__ __align__(8)  float sdel[64];
    __shared__ float sb1[64];

    const int tid = threadIdx.x;
    {
        const uint4* s = (const uint4*)Bt;
        uint4* d = (uint4*)smB;
        #pragma unroll
        for (int i = 0; i < 4; i++) d[tid + 128*i] = s[tid + 128*i];
    }
    if (tid < 64){
        float dd = 0.1f*w0[192+tid];
        sdel[tid] = dd;
        sb1[tid]  = 0.1f*b1[tid];
        sw4[tid]  = make_float4(0.1f*w0[tid], 0.1f*w0[64+tid],
                                0.1f*w0[128+tid], 0.1f*b0[tid]);
        float e8 = 8.f*dd;
        sc8[tid] = make_float2(cosf(e8), sinf(e8));
    }

    const int w = tid >> 5, l = tid & 31, g = l >> 2, t = l & 3;
    const int e  = w >> 1;
    const int cb = 32*(w & 1);
    const uint32_t lm_base = smem_u32(smB) +
        (uint32_t)(((((l >> 3) & 1)*64) + (l & 7)*8) * 2);
    const float cf = (float)(cb + g);

    __syncthreads();

    for (int tile = blockIdx.x; tile < ntiles; tile += gridDim.x){
        int eg = 2*tile + e;
        bool val = (eg < Etot);
        float4 ft = val ? g_feat[off+eg] : make_float4(0.f,0.f,0.f,0.f);

        float d[2][8][4];
        #pragma unroll
        for (int s = 0; s < 2; s++)
            #pragma unroll
            for (int n = 0; n < 8; n++)
                #pragma unroll
                for (int q = 0; q < 4; q++) d[s][n][q] = 0.f;

        #pragma unroll
        for (int k2 = 0; k2 < 4; k2++){
            const int hA = 2*t + 16*k2;
            uint32_t aH[2][4];
            // two h-pairs: (hA,hA+1) -> aH[*][0..1], (hA+8,hA+9) -> aH[*][2..3]
            #pragma unroll
            for (int j = 0; j < 2; j++){
                int hp = hA + 8*j;
                float4 s0 = sw4[hp], s1 = sw4[hp+1];
                float2 r0 = sc8[hp], r1 = sc8[hp+1];
                float2 dl = *(const float2*)&sdel[hp];
                float base0 = fmaf(ft.x, s0.x, fmaf(ft.y, s0.y, fmaf(ft.z, s0.z, s0.w)));
                float base1 = fmaf(ft.x, s1.x, fmaf(ft.y, s1.y, fmaf(ft.z, s1.z, s1.w)));
                float a0 = fmaf(cf, dl.x, base0);
                float a1 = fmaf(cf, dl.y, base1);
                float sA0 = __sinf(a0), cA0 = __cosf(a0);
                float sA1 = __sinf(a1), cA1 = __cosf(a1);
                // rotate by 8*del three times
                float sB0 = fmaf(sA0, r0.x,  cA0*r0.y);
                float cB0 = fmaf(cA0, r0.x, -sA0*r0.y);
                float sB1 = fmaf(sA1, r1.x,  cA1*r1.y);
                float cB1 = fmaf(cA1, r1.x, -sA1*r1.y);
                float sC0 = fmaf(sB0, r0.x,  cB0*r0.y);
                float cC0 = fmaf(cB0, r0.x, -sB0*r0.y);
                float sC1 = fmaf(sB1, r1.x,  cB1*r1.y);
                float cC1 = fmaf(cB1, r1.x, -sB1*r1.y);
                float sD0 = fmaf(sC0, r0.x,  cC0*r0.y);
                float sD1 = fmaf(sC1, r1.x,  cC1*r1.y);
                aH[0][2*j+0] = packh2(sA0, sA1);   // c = cf
                aH[0][2*j+1] = packh2(sB0, sB1);   // c = cf+8
                aH[1][2*j+0] = packh2(sC0, sC1);   // c = cf+16
                aH[1][2*j+1] = packh2(sD0, sD1);   // c = cf+24
            }
            uint32_t lma = lm_base + (uint32_t)(k2*8)*256u;
            #pragma unroll
            for (int nt = 0; nt < 8; nt++){
                uint32_t r0, r1;
                asm volatile("ldmatrix.sync.aligned.m8n8.x2.trans.shared.b16 "
                             "{%0,%1}, [%2];"
                             : "=r"(r0), "=r"(r1) : "r"(lma));
                lma += 256u;
                mma16816(d[0][nt], aH[0], r0, r1);
                mma16816(d[1][nt], aH[1], r0, r1);
            }
        }

        // ---- epilogue ----
        int sn = val ? g_src[off+eg] : 0;
        const float* yrow = &g_Yn[sn*YST];
        float m00 = 0.f, m01 = 0.f, m10 = 0.f, m11 = 0.f;
        #pragma unroll
        for (int nt = 0; nt < 8; nt++){
            int col = 2*t + 8*nt;
            float2 bv = *(const float2*)&sb1[col];
            float2 yv = val ? *(const float2*)&yrow[col] : make_float2(0.f, 0.f);
            m00 += __sinf(d[0][nt][0]+bv.x)*yv.x + __sinf(d[0][nt][1]+bv.y)*yv.y;
            m01 += __sinf(d[0][nt][2]+bv.x)*yv.x + __sinf(d[0][nt][3]+bv.y)*yv.y;
            m10 += __sinf(d[1][nt][0]+bv.x)*yv.x + __sinf(d[1][nt][1]+bv.y)*yv.y;
            m11 += __sinf(d[1][nt][2]+bv.x)*yv.x + __sinf(d[1][nt][3]+bv.y)*yv.y;
        }
        m00 += __shfl_xor_sync(~0u, m00, 1); m00 += __shfl_xor_sync(~0u, m00, 2);
        m01 += __shfl_xor_sync(~0u, m01, 1); m01 += __shfl_xor_sync(~0u, m01, 2);
        m10 += __shfl_xor_sync(~0u, m10, 1); m10 += __shfl_xor_sync(~0u, m10, 2);
        m11 += __shfl_xor_sync(~0u, m11, 1); m11 += __shfl_xor_sync(~0u, m11, 2);
        if (t == 0 && val){
            int dst = g_dst[off+eg];
            float eb = yrow[64];
            atomicAdd(&acc[dst*HD + cb + g     ], m00 + eb);
            atomicAdd(&acc[dst*HD + cb + g + 8 ], m01 + eb);
            atomicAdd(&acc[dst*HD + cb + g + 16], m10 + eb);
            atomicAdd(&acc[dst*HD + cb + g + 24], m11 + eb);
        }
    }
}

// ---------------- post / pool / final ----------------
__global__ void k_post0(const float* __restrict__ acc, const float* __restrict__ bias){
    int i = blockIdx.x*blockDim.x + threadIdx.x;
    float v = sinf(OMEGA_ENC*(acc[i] + bias[i & 63]));
    g_h1[i] = v;
    g_pool[i] = (__float_as_uint(v) == 0x80000000u) ? 0.f : v;
}
__global__ void k_post(const float* __restrict__ acc, const float* __restrict__ bias,
                       float* __restrict__ out, int n){
    int i = blockIdx.x*blockDim.x + threadIdx.x;
    if (i < n) out[i] = sinf(OMEGA_ENC*(acc[i] + bias[i & 63]));
}
__device__ __forceinline__ void atomicMaxF(float* addr, float v){
    if (__float_as_uint(v) == 0x80000000u) v = 0.f;
    if (v >= 0.f) atomicMax((int*)addr, __float_as_int(v));
    else          atomicMin((unsigned int*)addr, __float_as_uint(v));
}
__global__ void k_pool(int E){
    int idx = blockIdx.x*blockDim.x + threadIdx.x;
    int e = idx >> 6, c = idx & 63;
    if (e >= E) return;
    atomicMaxF(&g_pool[g_dst[e]*HD + c], g_h1[g_src[e]*HD + c]);
}
__global__ void k_final(const float* __restrict__ w, const float* __restrict__ b,
                        float* __restrict__ out){
    int j = blockIdx.x, l = threadIdx.x;
    float s = b[l];
    #pragma unroll
    for (int c = 0; c < HD; c++) s += g_h2[j*HD+c]*w[c*LATD+l];
    out[j*LATD+l] = sinf(OMEGA_ENC*s);
}

// ---------------- launch ----------------
extern "C" void kernel_launch(void* const* d_in, const int* in_sizes, int n_in,
                              void* d_out, int out_size){
    int iPos = 1, iEi = 2;
    if (in_sizes[1] == in_sizes[0]) { iEi = 1; iPos = 2; }

    const float* x      = (const float*)d_in[0];
    const float* pos    = (const float*)d_in[iPos];
    const int*   ei     = (const int*)  d_in[iEi];
    const int*   ei1    = (const int*)  d_in[3];
    const float* pos1   = (const float*)d_in[4];
    const int*   keep   = (const int*)  d_in[5];
    const float* lin0_w = (const float*)d_in[6];
    const float* lin0_b = (const float*)d_in[7];
    const float* lin1_w = (const float*)d_in[8];
    const float* lin1_b = (const float*)d_in[9];
    const float* c0p[7]; for (int i = 0; i < 7; i++) c0p[i] = (const float*)d_in[10+i];
    const float* c1p[7]; for (int i = 0; i < 7; i++) c1p[i] = (const float*)d_in[17+i];

    int N0 = in_sizes[0] / 8;
    int E0 = in_sizes[iEi] / 2;
    int N1 = in_sizes[5];
    int E1 = in_sizes[3] / 2;
    int Et0 = E0 + N0, Et1 = E1 + N1;
    int nt0 = (Et0 + 1)/2, nt1 = (Et1 + 1)/2;
    float* out = (float*)d_out;

    float *acc0, *acc1, *h2, *w2p;
    __half* bt;
    cudaGetSymbolAddress((void**)&acc0, g_acc0);
    cudaGetSymbolAddress((void**)&acc1, g_acc1);
    cudaGetSymbolAddress((void**)&h2,   g_h2);
    cudaGetSymbolAddress((void**)&bt,   g_Bt);
    cudaGetSymbolAddress((void**)&w2p,  g_w2p);

    int g0 = nt0 < 592 ? nt0 : 592;
    int g1 = nt1 < 592 ? nt1 : 592;

    // fused setup grid
    int nbB  = 32;                                  // 8192 B-tile elems
    int nbW  = (2*W2R*SXF + 255)/256;               // padded w2
    int nbG0 = (Et0 + 255)/256;
    int nbG1 = (Et1 + 255)/256;
    int nbBW = nbB + nbW, nbBWG = nbBW + nbG0;
    k_setup<<<nbBWG + nbG1, 256>>>(c0p[2], c1p[2], c0p[4], c1p[4], c0p[5], c1p[5],
                                   ei, E0, Et0, pos, ei1, E1, Et1, pos1,
                                   nbB, nbBW, nbBWG);
    k_encY <<<(N0 + 3)/4, 256>>>(x, pos, lin0_w, lin0_b, w2p, N0);

    // ---- conv0 ----
    k_convTC<<<g0, 128>>>(c0p[0], c0p[1], c0p[3], bt, Et0, nt0, 0, acc0);
    k_post0 <<<(N0*HD)/256, 256>>>(acc0, c0p[6]);

    // ---- pool ----
    k_pool<<<(E0*HD + 255)/256, 256>>>(E0);
    k_xf1Y<<<N1, 128>>>(keep, pos1, w2p + W2R*SXF);

    // ---- conv1 ----
    k_convTC<<<g1, 128>>>(c1p[0], c1p[1], c1p[3], bt + 4096, Et1, nt1, Et0, acc1);
    k_post  <<<(N1*HD + 255)/256, 256>>>(acc1, c1p[6], h2, N1*HD);

    k_final<<<N1, LATD>>>(lin1_w, lin1_b, out);
}